// round 1
// baseline (speedup 1.0000x reference)
#include <cuda_runtime.h>

#define Nn 50000
#define Ee 640000
#define DIM 128
#define NC 6

typedef unsigned long long ull;

// ---------------- device scratch (no runtime allocation allowed) ----------------
__device__ float g_s[Nn * DIM];   // h + agg (GEMM1 input)
__device__ float g_z[Nn * DIM];   // intermediate
__device__ float g_h[Nn * DIM];   // layer output
__device__ float g_p[Nn * 8];     // per-node classifier proj (src half) + bias
__device__ float g_q[Nn * 8];     // per-node classifier proj (dst half)
__device__ int   g_rowptr[Nn + 1];
__device__ int   g_cnt[Nn];
__device__ int   g_neigh[Ee];

// ---------------- helpers ----------------
__device__ __forceinline__ ull ffma2(ull a, ull b, ull c) {
    ull d;
    asm("fma.rn.f32x2 %0, %1, %2, %3;" : "=l"(d) : "l"(a), "l"(b), "l"(c));
    return d;
}
__device__ __forceinline__ ull dup2(float f) {
    unsigned u = __float_as_uint(f);
    return ((ull)u << 32) | (ull)u;
}
__device__ __forceinline__ float2 ull2f2(ull v) {
    float2 r;
    r.x = __uint_as_float((unsigned)v);
    r.y = __uint_as_float((unsigned)(v >> 32));
    return r;
}

// ---------------- CSR build ----------------
__global__ void zero_cnt_kernel() {
    int i = blockIdx.x * blockDim.x + threadIdx.x;
    if (i < Nn) g_cnt[i] = 0;
}

__global__ void count_kernel(const int* __restrict__ ei) {
    int e = blockIdx.x * blockDim.x + threadIdx.x;
    if (e < Ee) atomicAdd(&g_cnt[ei[Ee + e]], 1);
}

__global__ void scan_kernel() {
    __shared__ int wsum[32];
    __shared__ int carry;
    int tid = threadIdx.x, lane = tid & 31, wid = tid >> 5;
    if (tid == 0) carry = 0;
    __syncthreads();
    for (int base = 0; base < Nn; base += 1024) {
        int i = base + tid;
        int v = (i < Nn) ? g_cnt[i] : 0;
        int x = v;
        #pragma unroll
        for (int off = 1; off < 32; off <<= 1) {
            int y = __shfl_up_sync(0xffffffffu, x, off);
            if (lane >= off) x += y;
        }
        if (lane == 31) wsum[wid] = x;
        __syncthreads();
        if (wid == 0) {
            int t = wsum[lane];
            #pragma unroll
            for (int off = 1; off < 32; off <<= 1) {
                int y = __shfl_up_sync(0xffffffffu, t, off);
                if (lane >= off) t += y;
            }
            wsum[lane] = t;
        }
        __syncthreads();
        int woff = (wid > 0) ? wsum[wid - 1] : 0;
        int excl = carry + woff + x - v;
        if (i < Nn) { g_rowptr[i] = excl; g_cnt[i] = 0; }
        __syncthreads();
        if (tid == 0) carry += wsum[31];
        __syncthreads();
    }
    if (tid == 0) g_rowptr[Nn] = Ee;
}

__global__ void scatter_kernel(const int* __restrict__ ei) {
    int e = blockIdx.x * blockDim.x + threadIdx.x;
    if (e < Ee) {
        int d = ei[Ee + e];
        int slot = atomicAdd(&g_cnt[d], 1);
        g_neigh[g_rowptr[d] + slot] = ei[e];
    }
}

// ---------------- aggregation: s[i] = h[i] + sum_{j in in(i)} h[j] ----------------
__global__ void agg_kernel(const float* __restrict__ hin, float* __restrict__ sout) {
    int w = (blockIdx.x * blockDim.x + threadIdx.x) >> 5;
    int lane = threadIdx.x & 31;
    if (w >= Nn) return;
    const float4* hp = (const float4*)hin;
    float4 a = __ldg(&hp[(size_t)w * 32 + lane]);
    float x0 = a.x, x1 = a.y, x2 = a.z, x3 = a.w;
    int beg = g_rowptr[w], end = g_rowptr[w + 1];
    int e = beg;
    for (; e + 1 < end; e += 2) {
        int j0 = g_neigh[e], j1 = g_neigh[e + 1];
        float4 v0 = __ldg(&hp[(size_t)j0 * 32 + lane]);
        float4 v1 = __ldg(&hp[(size_t)j1 * 32 + lane]);
        x0 += v0.x; x1 += v0.y; x2 += v0.z; x3 += v0.w;
        x0 += v1.x; x1 += v1.y; x2 += v1.z; x3 += v1.w;
    }
    if (e < end) {
        int j = g_neigh[e];
        float4 v = __ldg(&hp[(size_t)j * 32 + lane]);
        x0 += v.x; x1 += v.y; x2 += v.z; x3 += v.w;
    }
    ((float4*)sout)[(size_t)w * 32 + lane] = make_float4(x0, x1, x2, x3);
}

// ---------------- GEMM: out = epilogue(A[M,128] @ W[128,128]) ----------------
// MODE 0: z = A@W + b1; out = relu(g*(z-rm)*rsqrt(rv+eps)+beta)
// MODE 1: out = relu(A@W + bias)
// Uses packed f32x2 FMA (FFMA2). A tile stored value-duplicated in SMEM so the
// broadcast operand needs no per-use pack instruction.
template <int MODE>
__global__ __launch_bounds__(256, 1) void gemm_kernel(
    const float* __restrict__ A, const float* __restrict__ W,
    const float* __restrict__ bias, const float* __restrict__ g,
    const float* __restrict__ beta, const float* __restrict__ rm,
    const float* __restrict__ rv,
    float* __restrict__ out, int M)
{
    __shared__ __align__(16) ull   Asd[128 * 32];   // 32 KB: A duplicated, [m][k]
    __shared__ __align__(16) float Bs[32 * 128];    // 16 KB: [k][n]

    int tid = threadIdx.x;
    int row0 = blockIdx.x * 128;
    int ty = tid >> 4, tx = tid & 15;
    int ty8 = ty * 8, col0 = tx * 8;

    ull acc[8][4];
    #pragma unroll
    for (int i = 0; i < 8; i++)
        #pragma unroll
        for (int j = 0; j < 4; j++) acc[i][j] = 0ULL;

    for (int kc = 0; kc < 4; kc++) {
        int k0 = kc * 32;
        // load A chunk 128x32 -> duplicated SMEM
        #pragma unroll
        for (int it = 0; it < 4; it++) {
            int idx = tid + it * 256;       // 0..1023
            int r = idx >> 3;
            int c4 = (idx & 7) << 2;
            int gr = row0 + r;
            float4 v = make_float4(0.f, 0.f, 0.f, 0.f);
            if (gr < M) v = *(const float4*)(A + (size_t)gr * DIM + k0 + c4);
            ulonglong2 w0, w1;
            w0.x = dup2(v.x); w0.y = dup2(v.y);
            w1.x = dup2(v.z); w1.y = dup2(v.w);
            *(ulonglong2*)&Asd[r * 32 + c4]     = w0;
            *(ulonglong2*)&Asd[r * 32 + c4 + 2] = w1;
        }
        // load B chunk 32x128
        #pragma unroll
        for (int it = 0; it < 4; it++) {
            int idx = tid + it * 256;
            int kk = idx >> 5;
            int c4 = (idx & 31) << 2;
            *(float4*)&Bs[kk * DIM + c4] =
                *(const float4*)(W + (size_t)(k0 + kk) * DIM + c4);
        }
        __syncthreads();

        #pragma unroll
        for (int k = 0; k < 32; k += 2) {
            ulonglong2 areg[8];
            #pragma unroll
            for (int i = 0; i < 8; i++)
                areg[i] = *(const ulonglong2*)&Asd[(ty8 + i) * 32 + k];
            ulonglong2 b0A = *(const ulonglong2*)&Bs[k * DIM + col0];
            ulonglong2 b0B = *(const ulonglong2*)&Bs[k * DIM + col0 + 4];
            ulonglong2 b1A = *(const ulonglong2*)&Bs[(k + 1) * DIM + col0];
            ulonglong2 b1B = *(const ulonglong2*)&Bs[(k + 1) * DIM + col0 + 4];
            #pragma unroll
            for (int i = 0; i < 8; i++) {
                acc[i][0] = ffma2(areg[i].x, b0A.x, acc[i][0]);
                acc[i][1] = ffma2(areg[i].x, b0A.y, acc[i][1]);
                acc[i][2] = ffma2(areg[i].x, b0B.x, acc[i][2]);
                acc[i][3] = ffma2(areg[i].x, b0B.y, acc[i][3]);
            }
            #pragma unroll
            for (int i = 0; i < 8; i++) {
                acc[i][0] = ffma2(areg[i].y, b1A.x, acc[i][0]);
                acc[i][1] = ffma2(areg[i].y, b1A.y, acc[i][1]);
                acc[i][2] = ffma2(areg[i].y, b1B.x, acc[i][2]);
                acc[i][3] = ffma2(areg[i].y, b1B.y, acc[i][3]);
            }
        }
        __syncthreads();
    }

    // epilogue
    float sc[8], sh[8];
    #pragma unroll
    for (int j = 0; j < 8; j++) {
        int c = col0 + j;
        if (MODE == 0) {
            float s = g[c] * rsqrtf(rv[c] + 1e-5f);
            sc[j] = s;
            sh[j] = (bias[c] - rm[c]) * s + beta[c];
        } else {
            sc[j] = 1.0f;
            sh[j] = bias[c];
        }
    }
    #pragma unroll
    for (int i = 0; i < 8; i++) {
        int gr = row0 + ty8 + i;
        if (gr >= M) continue;
        float o[8];
        #pragma unroll
        for (int jp = 0; jp < 4; jp++) {
            float2 v = ull2f2(acc[i][jp]);
            o[jp * 2]     = fmaxf(fmaf(v.x, sc[jp * 2],     sh[jp * 2]),     0.f);
            o[jp * 2 + 1] = fmaxf(fmaf(v.y, sc[jp * 2 + 1], sh[jp * 2 + 1]), 0.f);
        }
        float4* op = (float4*)(out + (size_t)gr * DIM + col0);
        op[0] = make_float4(o[0], o[1], o[2], o[3]);
        op[1] = make_float4(o[4], o[5], o[6], o[7]);
    }
}

// ---------------- classifier projections: p = h@Wtop + b, q = h@Wbot ----------------
__global__ void pq_kernel(const float* __restrict__ h, const float* __restrict__ clsW,
                          const float* __restrict__ clsb) {
    __shared__ float sW[256 * NC];
    int tid = threadIdx.x;
    for (int i = tid; i < 256 * NC; i += blockDim.x) sW[i] = clsW[i];
    __syncthreads();
    int w = (blockIdx.x * blockDim.x + tid) >> 5;
    int lane = tid & 31;
    if (w >= Nn) return;
    float4 a = __ldg(&((const float4*)h)[(size_t)w * 32 + lane]);
    int r = lane * 4;
    float accP[NC], accQ[NC];
    #pragma unroll
    for (int c = 0; c < NC; c++) {
        accP[c] = a.x * sW[r * NC + c] + a.y * sW[(r + 1) * NC + c]
                + a.z * sW[(r + 2) * NC + c] + a.w * sW[(r + 3) * NC + c];
        accQ[c] = a.x * sW[(128 + r) * NC + c] + a.y * sW[(129 + r) * NC + c]
                + a.z * sW[(130 + r) * NC + c] + a.w * sW[(131 + r) * NC + c];
    }
    #pragma unroll
    for (int off = 16; off > 0; off >>= 1) {
        #pragma unroll
        for (int c = 0; c < NC; c++) {
            accP[c] += __shfl_xor_sync(0xffffffffu, accP[c], off);
            accQ[c] += __shfl_xor_sync(0xffffffffu, accQ[c], off);
        }
    }
    if (lane == 0) {
        #pragma unroll
        for (int c = 0; c < NC; c++) {
            g_p[w * 8 + c] = accP[c] + clsb[c];
            g_q[w * 8 + c] = accQ[c];
        }
    }
}

// ---------------- final: write e = concat(h[src],h[dst]) and out = p[src]+q[dst] ----------------
__global__ void final_kernel(const float* __restrict__ h, const int* __restrict__ ei,
                             float* __restrict__ out0, float* __restrict__ eout) {
    int gt = blockIdx.x * blockDim.x + threadIdx.x;
    int e = gt >> 5, lane = gt & 31;
    if (e >= Ee) return;
    int s = ei[e], d = ei[Ee + e];
    const float4* hp = (const float4*)h;
    float4 a = __ldg(&hp[(size_t)s * 32 + lane]);
    float4 b = __ldg(&hp[(size_t)d * 32 + lane]);
    float4* ep = (float4*)(eout + (size_t)e * 256);
    ep[lane] = a;
    ep[32 + lane] = b;
    if (lane < NC) out0[(size_t)e * NC + lane] = g_p[s * 8 + lane] + g_q[d * 8 + lane];
}

// ---------------- launch ----------------
extern "C" void kernel_launch(void* const* d_in, const int* in_sizes, int n_in,
                              void* d_out, int out_size) {
    const float* x     = (const float*)d_in[0];
    const int*   ei    = (const int*)d_in[1];
    // d_in[2] = batch (unused)
    const float* c1_W1 = (const float*)d_in[3];
    const float* c1_b1 = (const float*)d_in[4];
    const float* c1_g  = (const float*)d_in[5];
    const float* c1_be = (const float*)d_in[6];
    const float* c1_rm = (const float*)d_in[7];
    const float* c1_rv = (const float*)d_in[8];
    const float* c1_W2 = (const float*)d_in[9];
    const float* c1_b2 = (const float*)d_in[10];
    const float* cv_W1 = (const float*)d_in[11];
    const float* cv_b1 = (const float*)d_in[12];
    const float* cv_g  = (const float*)d_in[13];
    const float* cv_be = (const float*)d_in[14];
    const float* cv_rm = (const float*)d_in[15];
    const float* cv_rv = (const float*)d_in[16];
    const float* cv_W2 = (const float*)d_in[17];
    const float* cv_b2 = (const float*)d_in[18];
    const float* lin_W = (const float*)d_in[19];
    const float* lin_b = (const float*)d_in[20];
    const float* cls_W = (const float*)d_in[21];
    const float* cls_b = (const float*)d_in[22];

    float* out0 = (float*)d_out;
    float* eout = out0 + (size_t)Ee * NC;

    void *ps, *pz, *ph;
    cudaGetSymbolAddress(&ps, g_s);
    cudaGetSymbolAddress(&pz, g_z);
    cudaGetSymbolAddress(&ph, g_h);
    float* S = (float*)ps;
    float* Z = (float*)pz;
    float* H = (float*)ph;

    const int GB = (Nn + 127) / 128;             // 391
    const int AGG_B = (Nn * 32 + 255) / 256;     // 6250
    const int FIN_B = (Ee * 32 + 255) / 256;     // 80000

    // CSR build (once per launch, reused by all 3 GIN layers)
    zero_cnt_kernel<<<(Nn + 255) / 256, 256>>>();
    count_kernel<<<(Ee + 255) / 256, 256>>>(ei);
    scan_kernel<<<1, 1024>>>();
    scatter_kernel<<<(Ee + 255) / 256, 256>>>(ei);

    // GIN layer 1 (input x, F_IN == DIM == 128)
    agg_kernel<<<AGG_B, 256>>>(x, S);
    gemm_kernel<0><<<GB, 256>>>(S, c1_W1, c1_b1, c1_g, c1_be, c1_rm, c1_rv, Z, Nn);
    gemm_kernel<1><<<GB, 256>>>(Z, c1_W2, c1_b2, 0, 0, 0, 0, H, Nn);

    // GIN layers 2..3
    for (int l = 0; l < 2; l++) {
        agg_kernel<<<AGG_B, 256>>>(H, S);
        gemm_kernel<0><<<GB, 256>>>(S, cv_W1 + (size_t)l * DIM * DIM, cv_b1 + l * DIM,
                                    cv_g + l * DIM, cv_be + l * DIM,
                                    cv_rm + l * DIM, cv_rv + l * DIM, Z, Nn);
        gemm_kernel<1><<<GB, 256>>>(Z, cv_W2 + (size_t)l * DIM * DIM, cv_b2 + l * DIM,
                                    0, 0, 0, 0, H, Nn);
    }

    // 2 linear layers
    gemm_kernel<1><<<GB, 256>>>(H, lin_W, lin_b, 0, 0, 0, 0, Z, Nn);
    gemm_kernel<1><<<GB, 256>>>(Z, lin_W + (size_t)DIM * DIM, lin_b + DIM, 0, 0, 0, 0, H, Nn);

    // classifier: out[e] = p[src] + q[dst]; e = concat(h[src], h[dst])
    pq_kernel<<<AGG_B, 256>>>(H, cls_W, cls_b);
    final_kernel<<<FIN_B, 256>>>(H, ei, out0, eout);
}

// round 3
// speedup vs baseline: 1.5543x; 1.5543x over previous
#include <cuda_runtime.h>
#include <cuda_bf16.h>
#include <cstdint>

#define Nn 50000
#define Nn2 50048        // padded rows (391 tiles of 128)
#define Ee 640000
#define DIM 128
#define NC 6

#define TSTRIDE 272                 // smem bytes per tile row (136 halves)
#define TILE_BYTES (128 * TSTRIDE)  // 34816

typedef unsigned long long ull;

// ---------------- device scratch (no runtime allocation allowed) ----------------
__device__ float g_h[Nn * DIM];                         // fp32 layer output
__device__ float g_p[Nn * 8];
__device__ float g_q[Nn * 8];
__device__ int   g_rowptr[Nn + 1];
__device__ int   g_cnt[Nn];
__device__ int   g_neigh[Ee];
// pre-split bf16 activations (rows >= Nn stay zero forever)
__device__ __align__(16) __nv_bfloat16 g_xhi[Nn2 * DIM];
__device__ __align__(16) __nv_bfloat16 g_xlo[Nn2 * DIM];
__device__ __align__(16) __nv_bfloat16 g_zhi[Nn2 * DIM];
__device__ __align__(16) __nv_bfloat16 g_zlo[Nn2 * DIM];
// pre-split, transposed ([n][k]) bf16 weights: slot g in [0,8)
__device__ __align__(16) __nv_bfloat16 g_Whi[8 * DIM * DIM];
__device__ __align__(16) __nv_bfloat16 g_Wlo[8 * DIM * DIM];

// ---------------- helpers ----------------
__device__ __forceinline__ uint32_t smem_u32(const void* p) {
    uint32_t a;
    asm("{ .reg .u64 t; cvta.to.shared.u64 t, %1; cvt.u32.u64 %0, t; }" : "=r"(a) : "l"(p));
    return a;
}
__device__ __forceinline__ void ldsm4(uint32_t* r, uint32_t addr) {
    asm volatile("ldmatrix.sync.aligned.m8n8.x4.shared.b16 {%0,%1,%2,%3}, [%4];"
                 : "=r"(r[0]), "=r"(r[1]), "=r"(r[2]), "=r"(r[3]) : "r"(addr));
}
__device__ __forceinline__ void ldsm2(uint32_t* r, uint32_t addr) {
    asm volatile("ldmatrix.sync.aligned.m8n8.x2.shared.b16 {%0,%1}, [%2];"
                 : "=r"(r[0]), "=r"(r[1]) : "r"(addr));
}
__device__ __forceinline__ void mma16816(float* c, const uint32_t* a, const uint32_t* b) {
    asm volatile(
        "mma.sync.aligned.m16n8k16.row.col.f32.bf16.bf16.f32 "
        "{%0,%1,%2,%3}, {%4,%5,%6,%7}, {%8,%9}, {%0,%1,%2,%3};"
        : "+f"(c[0]), "+f"(c[1]), "+f"(c[2]), "+f"(c[3])
        : "r"(a[0]), "r"(a[1]), "r"(a[2]), "r"(a[3]), "r"(b[0]), "r"(b[1]));
}
__device__ __forceinline__ uint32_t pack_bf16(float a, float b, float* ra, float* rb) {
    __nv_bfloat16 ha = __float2bfloat16(a);
    __nv_bfloat16 hb = __float2bfloat16(b);
    *ra = a - __bfloat162float(ha);
    *rb = b - __bfloat162float(hb);
    unsigned short ua = *(unsigned short*)&ha, ub = *(unsigned short*)&hb;
    return (uint32_t)ua | ((uint32_t)ub << 16);
}
__device__ __forceinline__ uint32_t pack_bf16_rn(float a, float b) {
    __nv_bfloat162 p = __floats2bfloat162_rn(a, b);
    return *(uint32_t*)&p;
}

// ---------------- CSR build ----------------
__global__ void zero_cnt_kernel() {
    int i = blockIdx.x * blockDim.x + threadIdx.x;
    if (i < Nn) g_cnt[i] = 0;
}

__global__ void count_kernel(const int* __restrict__ ei) {
    int e = blockIdx.x * blockDim.x + threadIdx.x;
    if (e < Ee) atomicAdd(&g_cnt[ei[Ee + e]], 1);
}

__global__ void scan_kernel() {
    __shared__ int wsum[32];
    __shared__ int carry;
    int tid = threadIdx.x, lane = tid & 31, wid = tid >> 5;
    if (tid == 0) carry = 0;
    __syncthreads();
    for (int base = 0; base < Nn; base += 1024) {
        int i = base + tid;
        int v = (i < Nn) ? g_cnt[i] : 0;
        int x = v;
        #pragma unroll
        for (int off = 1; off < 32; off <<= 1) {
            int y = __shfl_up_sync(0xffffffffu, x, off);
            if (lane >= off) x += y;
        }
        if (lane == 31) wsum[wid] = x;
        __syncthreads();
        if (wid == 0) {
            int t = wsum[lane];
            #pragma unroll
            for (int off = 1; off < 32; off <<= 1) {
                int y = __shfl_up_sync(0xffffffffu, t, off);
                if (lane >= off) t += y;
            }
            wsum[lane] = t;
        }
        __syncthreads();
        int woff = (wid > 0) ? wsum[wid - 1] : 0;
        int excl = carry + woff + x - v;
        if (i < Nn) { g_rowptr[i] = excl; g_cnt[i] = 0; }
        __syncthreads();
        if (tid == 0) carry += wsum[31];
        __syncthreads();
    }
    if (tid == 0) g_rowptr[Nn] = Ee;
}

__global__ void scatter_kernel(const int* __restrict__ ei) {
    int e = blockIdx.x * blockDim.x + threadIdx.x;
    if (e < Ee) {
        int d = ei[Ee + e];
        int slot = atomicAdd(&g_cnt[d], 1);
        g_neigh[g_rowptr[d] + slot] = ei[e];
    }
}

// ---------------- aggregation: x-buf = split_bf16(h[i] + sum_{j->i} h[j]) ----------------
__global__ void agg_kernel(const float* __restrict__ hin) {
    int w = (blockIdx.x * blockDim.x + threadIdx.x) >> 5;
    int lane = threadIdx.x & 31;
    if (w >= Nn) return;
    const float4* hp = (const float4*)hin;
    float4 a = __ldg(&hp[(size_t)w * 32 + lane]);
    float x0 = a.x, x1 = a.y, x2 = a.z, x3 = a.w;
    int beg = g_rowptr[w], end = g_rowptr[w + 1];
    int e = beg;
    for (; e + 1 < end; e += 2) {
        int j0 = g_neigh[e], j1 = g_neigh[e + 1];
        float4 v0 = __ldg(&hp[(size_t)j0 * 32 + lane]);
        float4 v1 = __ldg(&hp[(size_t)j1 * 32 + lane]);
        x0 += v0.x; x1 += v0.y; x2 += v0.z; x3 += v0.w;
        x0 += v1.x; x1 += v1.y; x2 += v1.z; x3 += v1.w;
    }
    if (e < end) {
        int j = g_neigh[e];
        float4 v = __ldg(&hp[(size_t)j * 32 + lane]);
        x0 += v.x; x1 += v.y; x2 += v.z; x3 += v.w;
    }
    float r0, r1, r2, r3;
    uint2 hw, lw;
    hw.x = pack_bf16(x0, x1, &r0, &r1);
    hw.y = pack_bf16(x2, x3, &r2, &r3);
    lw.x = pack_bf16_rn(r0, r1);
    lw.y = pack_bf16_rn(r2, r3);
    size_t off = (size_t)w * DIM + lane * 4;
    *(uint2*)(g_xhi + off) = hw;
    *(uint2*)(g_xlo + off) = lw;
}

// ---------------- weight prep: fp32 W[k][n] -> bf16 hi/lo transposed [n][k] ----------------
__global__ void prep_w_kernel(const float* w0, const float* w1, const float* w2,
                              const float* w3, const float* w4, const float* w5,
                              const float* w6, const float* w7) {
    int idx = blockIdx.x * blockDim.x + threadIdx.x;
    if (idx >= 8 * DIM * DIM) return;
    const float* ws[8] = {w0, w1, w2, w3, w4, w5, w6, w7};
    int g = idx >> 14, e = idx & 16383;
    int n = e >> 7, k = e & 127;          // output position [n][k]
    float v = ws[g][k * DIM + n];
    __nv_bfloat16 h = __float2bfloat16(v);
    float lo = v - __bfloat162float(h);
    g_Whi[g * 16384 + e] = h;
    g_Wlo[g * 16384 + e] = __float2bfloat16(lo);
}

// ---------------- HMMA GEMM: out = epilogue(A[M,128] @ W[128,128]) ----------------
// 3-term bf16 split with fp32 accumulation in mma fragments.
// MODE 0: BN+ReLU, MODE 1: bias+ReLU.
// AIN  0: A pre-split bf16 (Ahi_g/Alo_g), 1: A fp32 (Af), split in-kernel.
// OUTBF 1: emit bf16 hi/lo (next GEMM input). 0: emit fp32 (outf).
template <int MODE, int AIN, int OUTBF>
__global__ __launch_bounds__(512, 1) void gemm_mma(
    const __nv_bfloat16* __restrict__ Ahi_g, const __nv_bfloat16* __restrict__ Alo_g,
    const float* __restrict__ Af,
    const __nv_bfloat16* __restrict__ Bhi_g, const __nv_bfloat16* __restrict__ Blo_g,
    const float* __restrict__ bias, const float* __restrict__ gg,
    const float* __restrict__ beta, const float* __restrict__ rm,
    const float* __restrict__ rv,
    float* __restrict__ outf, __nv_bfloat16* __restrict__ outhi,
    __nv_bfloat16* __restrict__ outlo, int M, int ntiles)
{
    extern __shared__ __align__(16) char dyn[];   // 4 tiles: Ahi Alo Bhi Blo
    __shared__ float s_sc[DIM], s_sh[DIM];

    const int tid = threadIdx.x, lane = tid & 31, wid = tid >> 5;
    const uint32_t sbase = smem_u32(dyn);

    if (tid < DIM) {
        int c = tid;
        if (MODE == 0) {
            float s = gg[c] * rsqrtf(rv[c] + 1e-5f);
            s_sc[c] = s;
            s_sh[c] = (bias[c] - rm[c]) * s + beta[c];
        } else {
            s_sc[c] = 1.0f;
            s_sh[c] = bias[c];
        }
    }

    // B tiles: load once (persistent block)
    {
        const uint4* bh4 = (const uint4*)Bhi_g;
        const uint4* bl4 = (const uint4*)Blo_g;
        #pragma unroll
        for (int it = 0; it < 4; it++) {
            int i = tid + it * 512;                     // 0..2047
            uint32_t so = (uint32_t)(i >> 4) * TSTRIDE + (i & 15) * 16;
            *(uint4*)(dyn + 2 * TILE_BYTES + so) = __ldg(bh4 + i);
            *(uint4*)(dyn + 3 * TILE_BYTES + so) = __ldg(bl4 + i);
        }
    }

    const int wm = wid >> 2, wn = wid & 3;              // 4x4 warp grid
    const uint32_t aAddr = sbase + (uint32_t)(wm * 32 + (lane & 15)) * TSTRIDE + (lane >> 4) * 16;
    const uint32_t bAddr = sbase + 2 * TILE_BYTES +
                           (uint32_t)(wn * 32 + (lane & 7)) * TSTRIDE + ((lane >> 3) & 1) * 16;
    const int g4 = lane >> 2, tig = lane & 3;

    for (int t = blockIdx.x; t < ntiles; t += gridDim.x) {
        int row0 = t * 128;
        __syncthreads();    // all warps done reading A tile of previous iter

        if (AIN == 0) {
            const uint4* ah4 = (const uint4*)(Ahi_g + (size_t)row0 * DIM);
            const uint4* al4 = (const uint4*)(Alo_g + (size_t)row0 * DIM);
            #pragma unroll
            for (int it = 0; it < 4; it++) {
                int i = tid + it * 512;
                uint32_t so = (uint32_t)(i >> 4) * TSTRIDE + (i & 15) * 16;
                *(uint4*)(dyn + so) = __ldg(ah4 + i);
                *(uint4*)(dyn + TILE_BYTES + so) = __ldg(al4 + i);
            }
        } else {
            #pragma unroll
            for (int it = 0; it < 8; it++) {
                int i = tid + it * 512;                 // 0..4095
                int r = i >> 5, kc = (i & 31) * 4;
                float4 v = make_float4(0.f, 0.f, 0.f, 0.f);
                if (row0 + r < M) v = *(const float4*)(Af + (size_t)(row0 + r) * DIM + kc);
                float r0, r1, r2, r3;
                uint2 hw, lw;
                hw.x = pack_bf16(v.x, v.y, &r0, &r1);
                hw.y = pack_bf16(v.z, v.w, &r2, &r3);
                lw.x = pack_bf16_rn(r0, r1);
                lw.y = pack_bf16_rn(r2, r3);
                uint32_t so = (uint32_t)r * TSTRIDE + kc * 2;
                *(uint2*)(dyn + so) = hw;
                *(uint2*)(dyn + TILE_BYTES + so) = lw;
            }
        }
        __syncthreads();

        float acc[2][4][4];
        #pragma unroll
        for (int ma = 0; ma < 2; ma++)
            #pragma unroll
            for (int na = 0; na < 4; na++)
                #pragma unroll
                for (int q = 0; q < 4; q++) acc[ma][na][q] = 0.f;

        #pragma unroll
        for (int ks = 0; ks < 8; ks++) {
            uint32_t kb = ks * 32;
            uint32_t ah[2][4], al[2][4], bh[4][2], bl[4][2];
            ldsm4(ah[0], aAddr + kb);
            ldsm4(ah[1], aAddr + 16 * TSTRIDE + kb);
            ldsm4(al[0], aAddr + TILE_BYTES + kb);
            ldsm4(al[1], aAddr + TILE_BYTES + 16 * TSTRIDE + kb);
            #pragma unroll
            for (int na = 0; na < 4; na++) {
                ldsm2(bh[na], bAddr + na * 8 * TSTRIDE + kb);
                ldsm2(bl[na], bAddr + TILE_BYTES + na * 8 * TSTRIDE + kb);
            }
            #pragma unroll
            for (int ma = 0; ma < 2; ma++)
                #pragma unroll
                for (int na = 0; na < 4; na++) {
                    mma16816(acc[ma][na], ah[ma], bh[na]);
                    mma16816(acc[ma][na], ah[ma], bl[na]);
                    mma16816(acc[ma][na], al[ma], bh[na]);
                }
        }

        // epilogue from fragments
        #pragma unroll
        for (int ma = 0; ma < 2; ma++) {
            int r1 = row0 + wm * 32 + ma * 16 + g4;
            int r2 = r1 + 8;
            #pragma unroll
            for (int na = 0; na < 4; na++) {
                int col = wn * 32 + na * 8 + 2 * tig;
                float sc0 = s_sc[col], sc1 = s_sc[col + 1];
                float sh0 = s_sh[col], sh1 = s_sh[col + 1];
                float o0 = fmaxf(fmaf(acc[ma][na][0], sc0, sh0), 0.f);
                float o1 = fmaxf(fmaf(acc[ma][na][1], sc1, sh1), 0.f);
                float o2 = fmaxf(fmaf(acc[ma][na][2], sc0, sh0), 0.f);
                float o3 = fmaxf(fmaf(acc[ma][na][3], sc1, sh1), 0.f);
                if (OUTBF) {
                    if (r1 < M) {
                        float q0, q1;
                        *(uint32_t*)(outhi + (size_t)r1 * DIM + col) = pack_bf16(o0, o1, &q0, &q1);
                        *(uint32_t*)(outlo + (size_t)r1 * DIM + col) = pack_bf16_rn(q0, q1);
                    }
                    if (r2 < M) {
                        float q0, q1;
                        *(uint32_t*)(outhi + (size_t)r2 * DIM + col) = pack_bf16(o2, o3, &q0, &q1);
                        *(uint32_t*)(outlo + (size_t)r2 * DIM + col) = pack_bf16_rn(q0, q1);
                    }
                } else {
                    if (r1 < M) *(float2*)(outf + (size_t)r1 * DIM + col) = make_float2(o0, o1);
                    if (r2 < M) *(float2*)(outf + (size_t)r2 * DIM + col) = make_float2(o2, o3);
                }
            }
        }
    }
}

// ---------------- classifier projections ----------------
__global__ void pq_kernel(const float* __restrict__ h, const float* __restrict__ clsW,
                          const float* __restrict__ clsb) {
    __shared__ float sW[256 * NC];
    int tid = threadIdx.x;
    for (int i = tid; i < 256 * NC; i += blockDim.x) sW[i] = clsW[i];
    __syncthreads();
    int w = (blockIdx.x * blockDim.x + tid) >> 5;
    int lane = tid & 31;
    if (w >= Nn) return;
    float4 a = __ldg(&((const float4*)h)[(size_t)w * 32 + lane]);
    int r = lane * 4;
    float accP[NC], accQ[NC];
    #pragma unroll
    for (int c = 0; c < NC; c++) {
        accP[c] = a.x * sW[r * NC + c] + a.y * sW[(r + 1) * NC + c]
                + a.z * sW[(r + 2) * NC + c] + a.w * sW[(r + 3) * NC + c];
        accQ[c] = a.x * sW[(128 + r) * NC + c] + a.y * sW[(129 + r) * NC + c]
                + a.z * sW[(130 + r) * NC + c] + a.w * sW[(131 + r) * NC + c];
    }
    #pragma unroll
    for (int off = 16; off > 0; off >>= 1) {
        #pragma unroll
        for (int c = 0; c < NC; c++) {
            accP[c] += __shfl_xor_sync(0xffffffffu, accP[c], off);
            accQ[c] += __shfl_xor_sync(0xffffffffu, accQ[c], off);
        }
    }
    if (lane == 0) {
        #pragma unroll
        for (int c = 0; c < NC; c++) {
            g_p[w * 8 + c] = accP[c] + clsb[c];
            g_q[w * 8 + c] = accQ[c];
        }
    }
}

// ---------------- final: e = concat(h[src],h[dst]); out = p[src]+q[dst] ----------------
__global__ void final_kernel(const float* __restrict__ h, const int* __restrict__ ei,
                             float* __restrict__ out0, float* __restrict__ eout) {
    int gt = blockIdx.x * blockDim.x + threadIdx.x;
    int e = gt >> 5, lane = gt & 31;
    if (e >= Ee) return;
    int s = ei[e], d = ei[Ee + e];
    const float4* hp = (const float4*)h;
    float4 a = __ldg(&hp[(size_t)s * 32 + lane]);
    float4 b = __ldg(&hp[(size_t)d * 32 + lane]);
    float4* ep = (float4*)(eout + (size_t)e * 256);
    ep[lane] = a;
    ep[32 + lane] = b;
    if (lane < NC) out0[(size_t)e * NC + lane] = g_p[s * 8 + lane] + g_q[d * 8 + lane];
}

// ---------------- launch ----------------
extern "C" void kernel_launch(void* const* d_in, const int* in_sizes, int n_in,
                              void* d_out, int out_size) {
    const float* x     = (const float*)d_in[0];
    const int*   ei    = (const int*)d_in[1];
    const float* c1_W1 = (const float*)d_in[3];
    const float* c1_b1 = (const float*)d_in[4];
    const float* c1_g  = (const float*)d_in[5];
    const float* c1_be = (const float*)d_in[6];
    const float* c1_rm = (const float*)d_in[7];
    const float* c1_rv = (const float*)d_in[8];
    const float* c1_W2 = (const float*)d_in[9];
    const float* c1_b2 = (const float*)d_in[10];
    const float* cv_W1 = (const float*)d_in[11];
    const float* cv_b1 = (const float*)d_in[12];
    const float* cv_g  = (const float*)d_in[13];
    const float* cv_be = (const float*)d_in[14];
    const float* cv_rm = (const float*)d_in[15];
    const float* cv_rv = (const float*)d_in[16];
    const float* cv_W2 = (const float*)d_in[17];
    const float* cv_b2 = (const float*)d_in[18];
    const float* lin_W = (const float*)d_in[19];
    const float* lin_b = (const float*)d_in[20];
    const float* cls_W = (const float*)d_in[21];
    const float* cls_b = (const float*)d_in[22];

    float* out0 = (float*)d_out;
    float* eout = out0 + (size_t)Ee * NC;

    void *ph, *pxh, *pxl, *pzh, *pzl, *pwh, *pwl;
    cudaGetSymbolAddress(&ph, g_h);
    cudaGetSymbolAddress(&pxh, g_xhi);
    cudaGetSymbolAddress(&pxl, g_xlo);
    cudaGetSymbolAddress(&pzh, g_zhi);
    cudaGetSymbolAddress(&pzl, g_zlo);
    cudaGetSymbolAddress(&pwh, g_Whi);
    cudaGetSymbolAddress(&pwl, g_Wlo);
    float* H = (float*)ph;
    __nv_bfloat16* XH = (__nv_bfloat16*)pxh;
    __nv_bfloat16* XL = (__nv_bfloat16*)pxl;
    __nv_bfloat16* ZH = (__nv_bfloat16*)pzh;
    __nv_bfloat16* ZL = (__nv_bfloat16*)pzl;
    const __nv_bfloat16* WH = (const __nv_bfloat16*)pwh;
    const __nv_bfloat16* WL = (const __nv_bfloat16*)pwl;

    const int NT = Nn2 / 128;                    // 391 tiles
    const int GG = 148;                          // persistent grid
    const int AGG_B = (Nn * 32 + 255) / 256;
    const int FIN_B = (Ee * 32 + 255) / 256;
    const int SMEM_GEMM = 4 * TILE_BYTES;        // 139264

    cudaFuncSetAttribute(gemm_mma<0, 0, 1>, cudaFuncAttributeMaxDynamicSharedMemorySize, SMEM_GEMM);
    cudaFuncSetAttribute(gemm_mma<1, 0, 0>, cudaFuncAttributeMaxDynamicSharedMemorySize, SMEM_GEMM);
    cudaFuncSetAttribute(gemm_mma<1, 1, 1>, cudaFuncAttributeMaxDynamicSharedMemorySize, SMEM_GEMM);

    // CSR build + weight prep
    zero_cnt_kernel<<<(Nn + 255) / 256, 256>>>();
    count_kernel<<<(Ee + 255) / 256, 256>>>(ei);
    scan_kernel<<<1, 1024>>>();
    scatter_kernel<<<(Ee + 255) / 256, 256>>>(ei);
    prep_w_kernel<<<512, 256>>>(c1_W1, c1_W2,
                                cv_W1, cv_W1 + DIM * DIM,
                                cv_W2, cv_W2 + DIM * DIM,
                                lin_W, lin_W + DIM * DIM);
    // slots: 0=c1_W1 1=c1_W2 2=cvW1[0] 3=cvW1[1] 4=cvW2[0] 5=cvW2[1] 6=linW[0] 7=linW[1]

    // GIN layer 1
    agg_kernel<<<AGG_B, 256>>>(x);
    gemm_mma<0, 0, 1><<<GG, 512, SMEM_GEMM>>>(XH, XL, 0, WH + 0 * 16384, WL + 0 * 16384,
                                              c1_b1, c1_g, c1_be, c1_rm, c1_rv,
                                              0, ZH, ZL, Nn, NT);
    gemm_mma<1, 0, 0><<<GG, 512, SMEM_GEMM>>>(ZH, ZL, 0, WH + 1 * 16384, WL + 1 * 16384,
                                              c1_b2, 0, 0, 0, 0,
                                              H, 0, 0, Nn, NT);

    // GIN layers 2..3
    for (int l = 0; l < 2; l++) {
        agg_kernel<<<AGG_B, 256>>>(H);
        gemm_mma<0, 0, 1><<<GG, 512, SMEM_GEMM>>>(XH, XL, 0,
                                                  WH + (2 + l) * 16384, WL + (2 + l) * 16384,
                                                  cv_b1 + l * DIM, cv_g + l * DIM, cv_be + l * DIM,
                                                  cv_rm + l * DIM, cv_rv + l * DIM,
                                                  0, ZH, ZL, Nn, NT);
        gemm_mma<1, 0, 0><<<GG, 512, SMEM_GEMM>>>(ZH, ZL, 0,
                                                  WH + (4 + l) * 16384, WL + (4 + l) * 16384,
                                                  cv_b2 + l * DIM, 0, 0, 0, 0,
                                                  H, 0, 0, Nn, NT);
    }

    // 2 linear layers
    gemm_mma<1, 1, 1><<<GG, 512, SMEM_GEMM>>>(0, 0, H, WH + 6 * 16384, WL + 6 * 16384,
                                              lin_b, 0, 0, 0, 0,
                                              0, ZH, ZL, Nn, NT);
    gemm_mma<1, 0, 0><<<GG, 512, SMEM_GEMM>>>(ZH, ZL, 0, WH + 7 * 16384, WL + 7 * 16384,
                                              lin_b + DIM, 0, 0, 0, 0,
                                              H, 0, 0, Nn, NT);

    // classifier
    pq_kernel<<<AGG_B, 256>>>(H, cls_W, cls_b);
    final_kernel<<<FIN_B, 256>>>(H, ei, out0, eout);
}

// round 4
// speedup vs baseline: 1.6550x; 1.0648x over previous
#include <cuda_runtime.h>
#include <cuda_bf16.h>
#include <cstdint>

#define Nn 50000
#define Nn2 50048
#define Ee 640000
#define DIM 128
#define NC 6

#define TSTRIDE 272                 // smem bytes per tile row (136 halves)
#define TILE_BYTES (128 * TSTRIDE)  // 34816
#define SCAN_NB 98                  // ceil(50000/512)

typedef unsigned long long ull;

// ---------------- device scratch ----------------
__device__ float g_h[Nn * DIM];     // fp32 layer output
__device__ float g_hb[Nn * DIM];    // second fp32 buffer (ping-pong)
__device__ float g_p[Nn * 8];
__device__ float g_q[Nn * 8];
__device__ int   g_rowptr[Nn + 1];
__device__ int   g_cnt[Nn];
__device__ int   g_bsum[128];
__device__ int   g_neigh[Ee];
__device__ __align__(16) __nv_bfloat16 g_Whi[8 * DIM * DIM];
__device__ __align__(16) __nv_bfloat16 g_Wlo[8 * DIM * DIM];

// ---------------- helpers ----------------
__device__ __forceinline__ uint32_t smem_u32(const void* p) {
    uint32_t a;
    asm("{ .reg .u64 t; cvta.to.shared.u64 t, %1; cvt.u32.u64 %0, t; }" : "=r"(a) : "l"(p));
    return a;
}
__device__ __forceinline__ void ldsm4(uint32_t* r, uint32_t addr) {
    asm volatile("ldmatrix.sync.aligned.m8n8.x4.shared.b16 {%0,%1,%2,%3}, [%4];"
                 : "=r"(r[0]), "=r"(r[1]), "=r"(r[2]), "=r"(r[3]) : "r"(addr));
}
__device__ __forceinline__ void ldsm2(uint32_t* r, uint32_t addr) {
    asm volatile("ldmatrix.sync.aligned.m8n8.x2.shared.b16 {%0,%1}, [%2];"
                 : "=r"(r[0]), "=r"(r[1]) : "r"(addr));
}
__device__ __forceinline__ void mma16816(float* c, const uint32_t* a, const uint32_t* b) {
    asm volatile(
        "mma.sync.aligned.m16n8k16.row.col.f32.bf16.bf16.f32 "
        "{%0,%1,%2,%3}, {%4,%5,%6,%7}, {%8,%9}, {%0,%1,%2,%3};"
        : "+f"(c[0]), "+f"(c[1]), "+f"(c[2]), "+f"(c[3])
        : "r"(a[0]), "r"(a[1]), "r"(a[2]), "r"(a[3]), "r"(b[0]), "r"(b[1]));
}
__device__ __forceinline__ uint32_t pack_bf16(float a, float b, float* ra, float* rb) {
    __nv_bfloat16 ha = __float2bfloat16(a);
    __nv_bfloat16 hb = __float2bfloat16(b);
    *ra = a - __bfloat162float(ha);
    *rb = b - __bfloat162float(hb);
    unsigned short ua = *(unsigned short*)&ha, ub = *(unsigned short*)&hb;
    return (uint32_t)ua | ((uint32_t)ub << 16);
}
__device__ __forceinline__ uint32_t pack_bf16_rn(float a, float b) {
    __nv_bfloat162 p = __floats2bfloat162_rn(a, b);
    return *(uint32_t*)&p;
}

// ---------------- CSR build ----------------
__global__ void zero_cnt_kernel() {
    int i = blockIdx.x * blockDim.x + threadIdx.x;
    if (i < Nn / 4) ((int4*)g_cnt)[i] = make_int4(0, 0, 0, 0);
}

__global__ void count_kernel(const int* __restrict__ ei) {
    int e = blockIdx.x * blockDim.x + threadIdx.x;
    if (e < Ee) atomicAdd(&g_cnt[ei[Ee + e]], 1);
}

// block-local exclusive scan; writes block totals
__global__ void scan1_kernel() {
    __shared__ int ws[16];
    int tid = threadIdx.x, lane = tid & 31, w = tid >> 5;
    int i = blockIdx.x * 512 + tid;
    int v = (i < Nn) ? g_cnt[i] : 0;
    int x = v;
    #pragma unroll
    for (int off = 1; off < 32; off <<= 1) {
        int y = __shfl_up_sync(0xffffffffu, x, off);
        if (lane >= off) x += y;
    }
    if (lane == 31) ws[w] = x;
    __syncthreads();
    if (w == 0) {
        int t = (lane < 16) ? ws[lane] : 0;
        #pragma unroll
        for (int off = 1; off < 16; off <<= 1) {
            int y = __shfl_up_sync(0xffffffffu, t, off);
            if (lane >= off) t += y;
        }
        if (lane < 16) ws[lane] = t;
    }
    __syncthreads();
    int excl = (w ? ws[w - 1] : 0) + x - v;
    if (i < Nn) { g_rowptr[i] = excl; g_cnt[i] = 0; }
    if (tid == 0) g_bsum[blockIdx.x] = ws[15];
}

// exclusive scan of block sums (1 block, 128 threads)
__global__ void scan2_kernel() {
    __shared__ int ws2[4];
    int tid = threadIdx.x, lane = tid & 31, w = tid >> 5;
    int v = (tid < SCAN_NB) ? g_bsum[tid] : 0;
    int x = v;
    #pragma unroll
    for (int off = 1; off < 32; off <<= 1) {
        int y = __shfl_up_sync(0xffffffffu, x, off);
        if (lane >= off) x += y;
    }
    if (lane == 31) ws2[w] = x;
    __syncthreads();
    if (w == 0) {
        int t = (lane < 4) ? ws2[lane] : 0;
        #pragma unroll
        for (int off = 1; off < 4; off <<= 1) {
            int y = __shfl_up_sync(0xffffffffu, t, off);
            if (lane >= off) t += y;
        }
        if (lane < 4) ws2[lane] = t;
    }
    __syncthreads();
    int excl = (w ? ws2[w - 1] : 0) + x - v;
    if (tid < SCAN_NB) g_bsum[tid] = excl;
}

__global__ void scan3_kernel() {
    int i = blockIdx.x * 512 + threadIdx.x;
    if (i < Nn) g_rowptr[i] += g_bsum[blockIdx.x];
    if (i == 0) g_rowptr[Nn] = Ee;
}

__global__ void scatter_kernel(const int* __restrict__ ei) {
    int e = blockIdx.x * blockDim.x + threadIdx.x;
    if (e < Ee) {
        int d = ei[Ee + e];
        int slot = atomicAdd(&g_cnt[d], 1);
        g_neigh[g_rowptr[d] + slot] = ei[e];
    }
}

// ---------------- weight prep: fp32 W[k][n] -> bf16 hi/lo transposed [n][k] ----------------
__global__ void prep_w_kernel(const float* w0, const float* w1, const float* w2,
                              const float* w3, const float* w4, const float* w5,
                              const float* w6, const float* w7) {
    int idx = blockIdx.x * blockDim.x + threadIdx.x;
    if (idx >= 8 * DIM * DIM) return;
    const float* ws[8] = {w0, w1, w2, w3, w4, w5, w6, w7};
    int g = idx >> 14, e = idx & 16383;
    int n = e >> 7, k = e & 127;
    float v = ws[g][k * DIM + n];
    __nv_bfloat16 h = __float2bfloat16(v);
    float lo = v - __bfloat162float(h);
    g_Whi[g * 16384 + e] = h;
    g_Wlo[g * 16384 + e] = __float2bfloat16(lo);
}

// ---------------- fused MLP (optionally with GIN aggregation front-end) ----------------
// AGG 1: A = split(Hin[i] + sum_{j->i} Hin[j]); AGG 0: A = split(Hin)
// MODE1 0: epilogue1 = BN+ReLU; MODE1 1: epilogue1 = bias+ReLU. Epilogue2 = bias+ReLU, fp32 out.
// SMEM regions: 0=Ahi 1=Alo 2=B1hi 3=B1lo 4=B2hi 5=B2lo
template <int AGG, int MODE1>
__global__ __launch_bounds__(512, 1) void fused_mlp(
    const float* __restrict__ Hin,
    const __nv_bfloat16* __restrict__ B1h, const __nv_bfloat16* __restrict__ B1l,
    const __nv_bfloat16* __restrict__ B2h, const __nv_bfloat16* __restrict__ B2l,
    const float* __restrict__ b1, const float* __restrict__ gg,
    const float* __restrict__ be, const float* __restrict__ rm,
    const float* __restrict__ rv, const float* __restrict__ b2,
    float* __restrict__ Hout, int M, int ntiles)
{
    extern __shared__ __align__(16) char dyn[];
    __shared__ float s_sc[DIM], s_sh[DIM], s_b2[DIM];

    const int tid = threadIdx.x, lane = tid & 31, wid = tid >> 5;
    const uint32_t sbase = smem_u32(dyn);

    if (tid < DIM) {
        int c = tid;
        if (MODE1 == 0) {
            float s = gg[c] * rsqrtf(rv[c] + 1e-5f);
            s_sc[c] = s;
            s_sh[c] = (b1[c] - rm[c]) * s + be[c];
        } else {
            s_sc[c] = 1.0f;
            s_sh[c] = b1[c];
        }
        s_b2[c] = b2[c];
    }

    // load both weight tile pairs once (persistent block)
    {
        const uint4* p1h = (const uint4*)B1h;
        const uint4* p1l = (const uint4*)B1l;
        const uint4* p2h = (const uint4*)B2h;
        const uint4* p2l = (const uint4*)B2l;
        #pragma unroll
        for (int it = 0; it < 4; it++) {
            int i = tid + it * 512;
            uint32_t so = (uint32_t)(i >> 4) * TSTRIDE + (i & 15) * 16;
            *(uint4*)(dyn + 2 * TILE_BYTES + so) = __ldg(p1h + i);
            *(uint4*)(dyn + 3 * TILE_BYTES + so) = __ldg(p1l + i);
            *(uint4*)(dyn + 4 * TILE_BYTES + so) = __ldg(p2h + i);
            *(uint4*)(dyn + 5 * TILE_BYTES + so) = __ldg(p2l + i);
        }
    }

    const int wm = wid >> 2, wn = wid & 3;
    const uint32_t aAddr = sbase + (uint32_t)(wm * 32 + (lane & 15)) * TSTRIDE + (lane >> 4) * 16;
    const uint32_t bAddr1 = sbase + 2 * TILE_BYTES +
                            (uint32_t)(wn * 32 + (lane & 7)) * TSTRIDE + ((lane >> 3) & 1) * 16;
    const uint32_t bAddr2 = bAddr1 + 2 * TILE_BYTES;
    const int g4 = lane >> 2, tig = lane & 3;
    const float4* hp = (const float4*)Hin;

    for (int t = blockIdx.x; t < ntiles; t += gridDim.x) {
        int row0 = t * 128;
        __syncthreads();   // prior-tile MMA2 done reading A smem

        if (AGG) {
            // gather-aggregate: warp per row, 8 rows per warp
            #pragma unroll
            for (int qr = 0; qr < 8; qr++) {
                int lr = wid * 8 + qr;
                int gr = row0 + lr;
                float x0 = 0.f, x1 = 0.f, x2 = 0.f, x3 = 0.f;
                if (gr < M) {
                    float4 a = __ldg(&hp[(size_t)gr * 32 + lane]);
                    x0 = a.x; x1 = a.y; x2 = a.z; x3 = a.w;
                    int beg = g_rowptr[gr], end = g_rowptr[gr + 1];
                    int e = beg;
                    for (; e + 1 < end; e += 2) {
                        int j0 = g_neigh[e], j1 = g_neigh[e + 1];
                        float4 v0 = __ldg(&hp[(size_t)j0 * 32 + lane]);
                        float4 v1 = __ldg(&hp[(size_t)j1 * 32 + lane]);
                        x0 += v0.x; x1 += v0.y; x2 += v0.z; x3 += v0.w;
                        x0 += v1.x; x1 += v1.y; x2 += v1.z; x3 += v1.w;
                    }
                    if (e < end) {
                        int j = g_neigh[e];
                        float4 v = __ldg(&hp[(size_t)j * 32 + lane]);
                        x0 += v.x; x1 += v.y; x2 += v.z; x3 += v.w;
                    }
                }
                float r0, r1, r2, r3;
                uint2 hw, lw;
                hw.x = pack_bf16(x0, x1, &r0, &r1);
                hw.y = pack_bf16(x2, x3, &r2, &r3);
                lw.x = pack_bf16_rn(r0, r1);
                lw.y = pack_bf16_rn(r2, r3);
                uint32_t so = (uint32_t)lr * TSTRIDE + lane * 8;
                *(uint2*)(dyn + so) = hw;
                *(uint2*)(dyn + TILE_BYTES + so) = lw;
            }
        } else {
            #pragma unroll
            for (int it = 0; it < 8; it++) {
                int i = tid + it * 512;
                int r = i >> 5, kc = (i & 31) * 4;
                float4 v = make_float4(0.f, 0.f, 0.f, 0.f);
                if (row0 + r < M) v = *(const float4*)(Hin + (size_t)(row0 + r) * DIM + kc);
                float r0, r1, r2, r3;
                uint2 hw, lw;
                hw.x = pack_bf16(v.x, v.y, &r0, &r1);
                hw.y = pack_bf16(v.z, v.w, &r2, &r3);
                lw.x = pack_bf16_rn(r0, r1);
                lw.y = pack_bf16_rn(r2, r3);
                uint32_t so = (uint32_t)r * TSTRIDE + kc * 2;
                *(uint2*)(dyn + so) = hw;
                *(uint2*)(dyn + TILE_BYTES + so) = lw;
            }
        }
        __syncthreads();

        // ---- MMA pass 1 ----
        float acc[2][4][4];
        #pragma unroll
        for (int ma = 0; ma < 2; ma++)
            #pragma unroll
            for (int na = 0; na < 4; na++)
                #pragma unroll
                for (int q = 0; q < 4; q++) acc[ma][na][q] = 0.f;

        #pragma unroll
        for (int ks = 0; ks < 8; ks++) {
            uint32_t kb = ks * 32;
            uint32_t ah[2][4], al[2][4], bh[4][2], bl[4][2];
            ldsm4(ah[0], aAddr + kb);
            ldsm4(ah[1], aAddr + 16 * TSTRIDE + kb);
            ldsm4(al[0], aAddr + TILE_BYTES + kb);
            ldsm4(al[1], aAddr + TILE_BYTES + 16 * TSTRIDE + kb);
            #pragma unroll
            for (int na = 0; na < 4; na++) {
                ldsm2(bh[na], bAddr1 + na * 8 * TSTRIDE + kb);
                ldsm2(bl[na], bAddr1 + TILE_BYTES + na * 8 * TSTRIDE + kb);
            }
            #pragma unroll
            for (int ma = 0; ma < 2; ma++)
                #pragma unroll
                for (int na = 0; na < 4; na++) {
                    mma16816(acc[ma][na], ah[ma], bh[na]);
                    mma16816(acc[ma][na], ah[ma], bl[na]);
                    mma16816(acc[ma][na], al[ma], bh[na]);
                }
        }
        __syncthreads();   // all warps done reading A tile

        // epilogue 1: scale/shift + ReLU, split, write Z into A smem regions
        #pragma unroll
        for (int ma = 0; ma < 2; ma++) {
            int lr1 = wm * 32 + ma * 16 + g4;
            int lr2 = lr1 + 8;
            #pragma unroll
            for (int na = 0; na < 4; na++) {
                int col = wn * 32 + na * 8 + 2 * tig;
                float sc0 = s_sc[col], sc1 = s_sc[col + 1];
                float sh0 = s_sh[col], sh1 = s_sh[col + 1];
                float o0 = fmaxf(fmaf(acc[ma][na][0], sc0, sh0), 0.f);
                float o1 = fmaxf(fmaf(acc[ma][na][1], sc1, sh1), 0.f);
                float o2 = fmaxf(fmaf(acc[ma][na][2], sc0, sh0), 0.f);
                float o3 = fmaxf(fmaf(acc[ma][na][3], sc1, sh1), 0.f);
                float q0, q1;
                uint32_t so1 = (uint32_t)lr1 * TSTRIDE + col * 2;
                uint32_t so2 = (uint32_t)lr2 * TSTRIDE + col * 2;
                *(uint32_t*)(dyn + so1) = pack_bf16(o0, o1, &q0, &q1);
                *(uint32_t*)(dyn + TILE_BYTES + so1) = pack_bf16_rn(q0, q1);
                *(uint32_t*)(dyn + so2) = pack_bf16(o2, o3, &q0, &q1);
                *(uint32_t*)(dyn + TILE_BYTES + so2) = pack_bf16_rn(q0, q1);
            }
        }
        __syncthreads();

        // ---- MMA pass 2 ----
        #pragma unroll
        for (int ma = 0; ma < 2; ma++)
            #pragma unroll
            for (int na = 0; na < 4; na++)
                #pragma unroll
                for (int q = 0; q < 4; q++) acc[ma][na][q] = 0.f;

        #pragma unroll
        for (int ks = 0; ks < 8; ks++) {
            uint32_t kb = ks * 32;
            uint32_t ah[2][4], al[2][4], bh[4][2], bl[4][2];
            ldsm4(ah[0], aAddr + kb);
            ldsm4(ah[1], aAddr + 16 * TSTRIDE + kb);
            ldsm4(al[0], aAddr + TILE_BYTES + kb);
            ldsm4(al[1], aAddr + TILE_BYTES + 16 * TSTRIDE + kb);
            #pragma unroll
            for (int na = 0; na < 4; na++) {
                ldsm2(bh[na], bAddr2 + na * 8 * TSTRIDE + kb);
                ldsm2(bl[na], bAddr2 + TILE_BYTES + na * 8 * TSTRIDE + kb);
            }
            #pragma unroll
            for (int ma = 0; ma < 2; ma++)
                #pragma unroll
                for (int na = 0; na < 4; na++) {
                    mma16816(acc[ma][na], ah[ma], bh[na]);
                    mma16816(acc[ma][na], ah[ma], bl[na]);
                    mma16816(acc[ma][na], al[ma], bh[na]);
                }
        }

        // epilogue 2: bias + ReLU -> fp32 global
        #pragma unroll
        for (int ma = 0; ma < 2; ma++) {
            int r1 = row0 + wm * 32 + ma * 16 + g4;
            int r2 = r1 + 8;
            #pragma unroll
            for (int na = 0; na < 4; na++) {
                int col = wn * 32 + na * 8 + 2 * tig;
                float sh0 = s_b2[col], sh1 = s_b2[col + 1];
                float o0 = fmaxf(acc[ma][na][0] + sh0, 0.f);
                float o1 = fmaxf(acc[ma][na][1] + sh1, 0.f);
                float o2 = fmaxf(acc[ma][na][2] + sh0, 0.f);
                float o3 = fmaxf(acc[ma][na][3] + sh1, 0.f);
                if (r1 < M) *(float2*)(Hout + (size_t)r1 * DIM + col) = make_float2(o0, o1);
                if (r2 < M) *(float2*)(Hout + (size_t)r2 * DIM + col) = make_float2(o2, o3);
            }
        }
    }
}

// ---------------- classifier projections ----------------
__global__ void pq_kernel(const float* __restrict__ h, const float* __restrict__ clsW,
                          const float* __restrict__ clsb) {
    __shared__ float sW[256 * NC];
    int tid = threadIdx.x;
    for (int i = tid; i < 256 * NC; i += blockDim.x) sW[i] = clsW[i];
    __syncthreads();
    int w = (blockIdx.x * blockDim.x + tid) >> 5;
    int lane = tid & 31;
    if (w >= Nn) return;
    float4 a = __ldg(&((const float4*)h)[(size_t)w * 32 + lane]);
    int r = lane * 4;
    float accP[NC], accQ[NC];
    #pragma unroll
    for (int c = 0; c < NC; c++) {
        accP[c] = a.x * sW[r * NC + c] + a.y * sW[(r + 1) * NC + c]
                + a.z * sW[(r + 2) * NC + c] + a.w * sW[(r + 3) * NC + c];
        accQ[c] = a.x * sW[(128 + r) * NC + c] + a.y * sW[(129 + r) * NC + c]
                + a.z * sW[(130 + r) * NC + c] + a.w * sW[(131 + r) * NC + c];
    }
    #pragma unroll
    for (int off = 16; off > 0; off >>= 1) {
        #pragma unroll
        for (int c = 0; c < NC; c++) {
            accP[c] += __shfl_xor_sync(0xffffffffu, accP[c], off);
            accQ[c] += __shfl_xor_sync(0xffffffffu, accQ[c], off);
        }
    }
    if (lane == 0) {
        #pragma unroll
        for (int c = 0; c < NC; c++) {
            g_p[w * 8 + c] = accP[c] + clsb[c];
            g_q[w * 8 + c] = accQ[c];
        }
    }
}

// ---------------- final: e = concat(h[src],h[dst]); out = p[src]+q[dst] ----------------
__global__ void final_kernel(const float* __restrict__ h, const int* __restrict__ ei,
                             float* __restrict__ out0, float* __restrict__ eout) {
    int gt = blockIdx.x * blockDim.x + threadIdx.x;
    int e = gt >> 5, lane = gt & 31;
    if (e >= Ee) return;
    int s = ei[e], d = ei[Ee + e];
    const float4* hp = (const float4*)h;
    float4 a = __ldg(&hp[(size_t)s * 32 + lane]);
    float4 b = __ldg(&hp[(size_t)d * 32 + lane]);
    float4* ep = (float4*)(eout + (size_t)e * 256);
    ep[lane] = a;
    ep[32 + lane] = b;
    if (lane < NC) out0[(size_t)e * NC + lane] = g_p[s * 8 + lane] + g_q[d * 8 + lane];
}

// ---------------- launch ----------------
extern "C" void kernel_launch(void* const* d_in, const int* in_sizes, int n_in,
                              void* d_out, int out_size) {
    const float* x     = (const float*)d_in[0];
    const int*   ei    = (const int*)d_in[1];
    const float* c1_W1 = (const float*)d_in[3];
    const float* c1_b1 = (const float*)d_in[4];
    const float* c1_g  = (const float*)d_in[5];
    const float* c1_be = (const float*)d_in[6];
    const float* c1_rm = (const float*)d_in[7];
    const float* c1_rv = (const float*)d_in[8];
    const float* c1_W2 = (const float*)d_in[9];
    const float* c1_b2 = (const float*)d_in[10];
    const float* cv_W1 = (const float*)d_in[11];
    const float* cv_b1 = (const float*)d_in[12];
    const float* cv_g  = (const float*)d_in[13];
    const float* cv_be = (const float*)d_in[14];
    const float* cv_rm = (const float*)d_in[15];
    const float* cv_rv = (const float*)d_in[16];
    const float* cv_W2 = (const float*)d_in[17];
    const float* cv_b2 = (const float*)d_in[18];
    const float* lin_W = (const float*)d_in[19];
    const float* lin_b = (const float*)d_in[20];
    const float* cls_W = (const float*)d_in[21];
    const float* cls_b = (const float*)d_in[22];

    float* out0 = (float*)d_out;
    float* eout = out0 + (size_t)Ee * NC;

    void *ph, *phb, *pwh, *pwl;
    cudaGetSymbolAddress(&ph, g_h);
    cudaGetSymbolAddress(&phb, g_hb);
    cudaGetSymbolAddress(&pwh, g_Whi);
    cudaGetSymbolAddress(&pwl, g_Wlo);
    float* H = (float*)ph;
    float* HB = (float*)phb;
    const __nv_bfloat16* WH = (const __nv_bfloat16*)pwh;
    const __nv_bfloat16* WL = (const __nv_bfloat16*)pwl;

    const int NT = Nn2 / 128;                 // 391 tiles
    const int GG = 148;                       // persistent grid
    const int AGG_B = (Nn * 32 + 255) / 256;
    const int FIN_B = (Ee * 32 + 255) / 256;
    const int SMEM_F = 6 * TILE_BYTES;        // 208896

    cudaFuncSetAttribute(fused_mlp<1, 0>, cudaFuncAttributeMaxDynamicSharedMemorySize, SMEM_F);
    cudaFuncSetAttribute(fused_mlp<0, 1>, cudaFuncAttributeMaxDynamicSharedMemorySize, SMEM_F);

    // CSR build + weight prep
    zero_cnt_kernel<<<(Nn / 4 + 255) / 256, 256>>>();
    count_kernel<<<(Ee + 255) / 256, 256>>>(ei);
    scan1_kernel<<<SCAN_NB, 512>>>();
    scan2_kernel<<<1, 128>>>();
    scan3_kernel<<<SCAN_NB, 512>>>();
    scatter_kernel<<<(Ee + 255) / 256, 256>>>(ei);
    prep_w_kernel<<<512, 256>>>(c1_W1, c1_W2,
                                cv_W1, cv_W1 + DIM * DIM,
                                cv_W2, cv_W2 + DIM * DIM,
                                lin_W, lin_W + DIM * DIM);
    // slots: 0=c1_W1 1=c1_W2 2=cvW1[0] 3=cvW1[1] 4=cvW2[0] 5=cvW2[1] 6=linW[0] 7=linW[1]

    // GIN layer 1 (x -> HB)
    fused_mlp<1, 0><<<GG, 512, SMEM_F>>>(x, WH + 0 * 16384, WL + 0 * 16384,
                                         WH + 1 * 16384, WL + 1 * 16384,
                                         c1_b1, c1_g, c1_be, c1_rm, c1_rv, c1_b2,
                                         HB, Nn, NT);
    // GIN layers 2..3 (ping-pong HB <-> H)
    fused_mlp<1, 0><<<GG, 512, SMEM_F>>>(HB, WH + 2 * 16384, WL + 2 * 16384,
                                         WH + 4 * 16384, WL + 4 * 16384,
                                         cv_b1, cv_g, cv_be, cv_rm, cv_rv, cv_b2,
                                         H, Nn, NT);
    fused_mlp<1, 0><<<GG, 512, SMEM_F>>>(H, WH + 3 * 16384, WL + 3 * 16384,
                                         WH + 5 * 16384, WL + 5 * 16384,
                                         cv_b1 + DIM, cv_g + DIM, cv_be + DIM,
                                         cv_rm + DIM, cv_rv + DIM, cv_b2 + DIM,
                                         HB, Nn, NT);
    // linear layers (HB -> H)
    fused_mlp<0, 1><<<GG, 512, SMEM_F>>>(HB, WH + 6 * 16384, WL + 6 * 16384,
                                         WH + 7 * 16384, WL + 7 * 16384,
                                         lin_b, 0, 0, 0, 0, lin_b + DIM,
                                         H, Nn, NT);

    // classifier
    pq_kernel<<<AGG_B, 256>>>(H, cls_W, cls_b);
    final_kernel<<<FIN_B, 256>>>(H, ei, out0, eout);
}

// round 5
// speedup vs baseline: 1.8247x; 1.1025x over previous
#include <cuda_runtime.h>
#include <cuda_bf16.h>
#include <cstdint>

#define Nn 50000
#define Nn2 50048
#define Ee 640000
#define DIM 128
#define NC 6

#define TSTRIDE 272                 // smem bytes per tile row (136 halves)
#define TILE_BYTES (128 * TSTRIDE)  // 34816
#define SCAN_NB 98                  // ceil(50000/512)

typedef unsigned long long ull;

// ---------------- device scratch ----------------
__device__ float g_h[Nn * DIM];     // fp32 activations (pq/final input)
__device__ float g_p[Nn * 8];
__device__ float g_q[Nn * 8];
__device__ int   g_rowptr[Nn + 1];
__device__ int   g_cnt[Nn];
__device__ int   g_bsum[128];
__device__ int   g_neigh[Ee];
// pre-split bf16 activations (rows >= Nn stay zero: never written)
__device__ __align__(16) __nv_bfloat16 g_xhi[Nn2 * DIM];
__device__ __align__(16) __nv_bfloat16 g_xlo[Nn2 * DIM];
__device__ __align__(16) __nv_bfloat16 g_x2hi[Nn2 * DIM];
__device__ __align__(16) __nv_bfloat16 g_x2lo[Nn2 * DIM];
__device__ __align__(16) __nv_bfloat16 g_Whi[8 * DIM * DIM];
__device__ __align__(16) __nv_bfloat16 g_Wlo[8 * DIM * DIM];

// ---------------- helpers ----------------
__device__ __forceinline__ uint32_t smem_u32(const void* p) {
    uint32_t a;
    asm("{ .reg .u64 t; cvta.to.shared.u64 t, %1; cvt.u32.u64 %0, t; }" : "=r"(a) : "l"(p));
    return a;
}
__device__ __forceinline__ void ldsm4(uint32_t* r, uint32_t addr) {
    asm volatile("ldmatrix.sync.aligned.m8n8.x4.shared.b16 {%0,%1,%2,%3}, [%4];"
                 : "=r"(r[0]), "=r"(r[1]), "=r"(r[2]), "=r"(r[3]) : "r"(addr));
}
__device__ __forceinline__ void ldsm2(uint32_t* r, uint32_t addr) {
    asm volatile("ldmatrix.sync.aligned.m8n8.x2.shared.b16 {%0,%1}, [%2];"
                 : "=r"(r[0]), "=r"(r[1]) : "r"(addr));
}
__device__ __forceinline__ void mma16816(float* c, const uint32_t* a, const uint32_t* b) {
    asm volatile(
        "mma.sync.aligned.m16n8k16.row.col.f32.bf16.bf16.f32 "
        "{%0,%1,%2,%3}, {%4,%5,%6,%7}, {%8,%9}, {%0,%1,%2,%3};"
        : "+f"(c[0]), "+f"(c[1]), "+f"(c[2]), "+f"(c[3])
        : "r"(a[0]), "r"(a[1]), "r"(a[2]), "r"(a[3]), "r"(b[0]), "r"(b[1]));
}
__device__ __forceinline__ uint32_t pack_bf16(float a, float b, float* ra, float* rb) {
    __nv_bfloat16 ha = __float2bfloat16(a);
    __nv_bfloat16 hb = __float2bfloat16(b);
    *ra = a - __bfloat162float(ha);
    *rb = b - __bfloat162float(hb);
    unsigned short ua = *(unsigned short*)&ha, ub = *(unsigned short*)&hb;
    return (uint32_t)ua | ((uint32_t)ub << 16);
}
__device__ __forceinline__ uint32_t pack_bf16_rn(float a, float b) {
    __nv_bfloat162 p = __floats2bfloat162_rn(a, b);
    return *(uint32_t*)&p;
}

// ---------------- CSR build ----------------
__global__ void zero_cnt_kernel() {
    int i = blockIdx.x * blockDim.x + threadIdx.x;
    if (i < Nn / 4) ((int4*)g_cnt)[i] = make_int4(0, 0, 0, 0);
}

__global__ void count_kernel(const int* __restrict__ ei) {
    int e = blockIdx.x * blockDim.x + threadIdx.x;
    if (e < Ee) atomicAdd(&g_cnt[ei[Ee + e]], 1);
}

__global__ void scan1_kernel() {
    __shared__ int ws[16];
    int tid = threadIdx.x, lane = tid & 31, w = tid >> 5;
    int i = blockIdx.x * 512 + tid;
    int v = (i < Nn) ? g_cnt[i] : 0;
    int x = v;
    #pragma unroll
    for (int off = 1; off < 32; off <<= 1) {
        int y = __shfl_up_sync(0xffffffffu, x, off);
        if (lane >= off) x += y;
    }
    if (lane == 31) ws[w] = x;
    __syncthreads();
    if (w == 0) {
        int t = (lane < 16) ? ws[lane] : 0;
        #pragma unroll
        for (int off = 1; off < 16; off <<= 1) {
            int y = __shfl_up_sync(0xffffffffu, t, off);
            if (lane >= off) t += y;
        }
        if (lane < 16) ws[lane] = t;
    }
    __syncthreads();
    int excl = (w ? ws[w - 1] : 0) + x - v;
    if (i < Nn) { g_rowptr[i] = excl; g_cnt[i] = 0; }
    if (tid == 0) g_bsum[blockIdx.x] = ws[15];
}

__global__ void scan2_kernel() {
    __shared__ int ws2[4];
    int tid = threadIdx.x, lane = tid & 31, w = tid >> 5;
    int v = (tid < SCAN_NB) ? g_bsum[tid] : 0;
    int x = v;
    #pragma unroll
    for (int off = 1; off < 32; off <<= 1) {
        int y = __shfl_up_sync(0xffffffffu, x, off);
        if (lane >= off) x += y;
    }
    if (lane == 31) ws2[w] = x;
    __syncthreads();
    if (w == 0) {
        int t = (lane < 4) ? ws2[lane] : 0;
        #pragma unroll
        for (int off = 1; off < 4; off <<= 1) {
            int y = __shfl_up_sync(0xffffffffu, t, off);
            if (lane >= off) t += y;
        }
        if (lane < 4) ws2[lane] = t;
    }
    __syncthreads();
    int excl = (w ? ws2[w - 1] : 0) + x - v;
    if (tid < SCAN_NB) g_bsum[tid] = excl;
}

__global__ void scan3_kernel() {
    int i = blockIdx.x * 512 + threadIdx.x;
    if (i < Nn) g_rowptr[i] += g_bsum[blockIdx.x];
    if (i == 0) g_rowptr[Nn] = Ee;
}

__global__ void scatter_kernel(const int* __restrict__ ei) {
    int e = blockIdx.x * blockDim.x + threadIdx.x;
    if (e < Ee) {
        int d = ei[Ee + e];
        int slot = atomicAdd(&g_cnt[d], 1);
        g_neigh[g_rowptr[d] + slot] = ei[e];
    }
}

// ---------------- weight prep ----------------
__global__ void prep_w_kernel(const float* w0, const float* w1, const float* w2,
                              const float* w3, const float* w4, const float* w5,
                              const float* w6, const float* w7) {
    int idx = blockIdx.x * blockDim.x + threadIdx.x;
    if (idx >= 8 * DIM * DIM) return;
    const float* ws[8] = {w0, w1, w2, w3, w4, w5, w6, w7};
    int g = idx >> 14, e = idx & 16383;
    int n = e >> 7, k = e & 127;
    float v = ws[g][k * DIM + n];
    __nv_bfloat16 h = __float2bfloat16(v);
    float lo = v - __bfloat162float(h);
    g_Whi[g * 16384 + e] = h;
    g_Wlo[g * 16384 + e] = __float2bfloat16(lo);
}

// ---------------- aggregation: (xhi,xlo) = split(h[i] + sum_{j->i} h[j]) ----------------
__global__ void agg_kernel(const float* __restrict__ hin,
                           __nv_bfloat16* __restrict__ xhi,
                           __nv_bfloat16* __restrict__ xlo) {
    int w = (blockIdx.x * blockDim.x + threadIdx.x) >> 5;
    int lane = threadIdx.x & 31;
    if (w >= Nn) return;
    const float4* hp = (const float4*)hin;
    float4 a = __ldg(&hp[(size_t)w * 32 + lane]);
    float x0 = a.x, x1 = a.y, x2 = a.z, x3 = a.w;
    int beg = g_rowptr[w], end = g_rowptr[w + 1];
    int e = beg;
    for (; e + 3 < end; e += 4) {
        int j0 = g_neigh[e], j1 = g_neigh[e + 1];
        int j2 = g_neigh[e + 2], j3 = g_neigh[e + 3];
        float4 v0 = __ldg(&hp[(size_t)j0 * 32 + lane]);
        float4 v1 = __ldg(&hp[(size_t)j1 * 32 + lane]);
        float4 v2 = __ldg(&hp[(size_t)j2 * 32 + lane]);
        float4 v3 = __ldg(&hp[(size_t)j3 * 32 + lane]);
        x0 += v0.x + v1.x + v2.x + v3.x;
        x1 += v0.y + v1.y + v2.y + v3.y;
        x2 += v0.z + v1.z + v2.z + v3.z;
        x3 += v0.w + v1.w + v2.w + v3.w;
    }
    for (; e < end; e++) {
        int j = g_neigh[e];
        float4 v = __ldg(&hp[(size_t)j * 32 + lane]);
        x0 += v.x; x1 += v.y; x2 += v.z; x3 += v.w;
    }
    float r0, r1, r2, r3;
    uint2 hw, lw;
    hw.x = pack_bf16(x0, x1, &r0, &r1);
    hw.y = pack_bf16(x2, x3, &r2, &r3);
    lw.x = pack_bf16_rn(r0, r1);
    lw.y = pack_bf16_rn(r2, r3);
    size_t off = (size_t)w * DIM + lane * 4;
    *(uint2*)(xhi + off) = hw;
    *(uint2*)(xlo + off) = lw;
}

// ---------------- fused dual-GEMM MLP ----------------
// A input: pre-split bf16 (Ahi/Alo), straight copies to smem.
// MODE1 0: epilogue1 = BN+ReLU; 1: bias+ReLU. Z overwrites A smem.
// OUTBF 0: epilogue2 -> fp32 Hout; 1: epilogue2 -> split bf16 (Ohi/Olo).
template <int MODE1, int OUTBF>
__global__ __launch_bounds__(512, 1) void fused_mlp(
    const __nv_bfloat16* __restrict__ Ahi_g, const __nv_bfloat16* __restrict__ Alo_g,
    const __nv_bfloat16* __restrict__ B1h, const __nv_bfloat16* __restrict__ B1l,
    const __nv_bfloat16* __restrict__ B2h, const __nv_bfloat16* __restrict__ B2l,
    const float* __restrict__ b1, const float* __restrict__ gg,
    const float* __restrict__ be, const float* __restrict__ rm,
    const float* __restrict__ rv, const float* __restrict__ b2,
    float* __restrict__ Hout, __nv_bfloat16* __restrict__ Ohi,
    __nv_bfloat16* __restrict__ Olo, int M, int ntiles)
{
    extern __shared__ __align__(16) char dyn[];
    __shared__ float s_sc[DIM], s_sh[DIM], s_b2[DIM];

    const int tid = threadIdx.x, lane = tid & 31, wid = tid >> 5;
    const uint32_t sbase = smem_u32(dyn);

    if (tid < DIM) {
        int c = tid;
        if (MODE1 == 0) {
            float s = gg[c] * rsqrtf(rv[c] + 1e-5f);
            s_sc[c] = s;
            s_sh[c] = (b1[c] - rm[c]) * s + be[c];
        } else {
            s_sc[c] = 1.0f;
            s_sh[c] = b1[c];
        }
        s_b2[c] = b2[c];
    }

    {   // weight tiles once (persistent block)
        const uint4* p1h = (const uint4*)B1h;
        const uint4* p1l = (const uint4*)B1l;
        const uint4* p2h = (const uint4*)B2h;
        const uint4* p2l = (const uint4*)B2l;
        #pragma unroll
        for (int it = 0; it < 4; it++) {
            int i = tid + it * 512;
            uint32_t so = (uint32_t)(i >> 4) * TSTRIDE + (i & 15) * 16;
            *(uint4*)(dyn + 2 * TILE_BYTES + so) = __ldg(p1h + i);
            *(uint4*)(dyn + 3 * TILE_BYTES + so) = __ldg(p1l + i);
            *(uint4*)(dyn + 4 * TILE_BYTES + so) = __ldg(p2h + i);
            *(uint4*)(dyn + 5 * TILE_BYTES + so) = __ldg(p2l + i);
        }
    }

    const int wm = wid >> 2, wn = wid & 3;
    const uint32_t aAddr = sbase + (uint32_t)(wm * 32 + (lane & 15)) * TSTRIDE + (lane >> 4) * 16;
    const uint32_t bAddr1 = sbase + 2 * TILE_BYTES +
                            (uint32_t)(wn * 32 + (lane & 7)) * TSTRIDE + ((lane >> 3) & 1) * 16;
    const uint32_t bAddr2 = bAddr1 + 2 * TILE_BYTES;
    const int g4 = lane >> 2, tig = lane & 3;

    for (int t = blockIdx.x; t < ntiles; t += gridDim.x) {
        int row0 = t * 128;
        __syncthreads();   // prior-tile MMA2 done reading A smem

        {   // A tiles: straight uint4 copies (pre-split, pre-zero-padded rows)
            const uint4* ah4 = (const uint4*)(Ahi_g + (size_t)row0 * DIM);
            const uint4* al4 = (const uint4*)(Alo_g + (size_t)row0 * DIM);
            #pragma unroll
            for (int it = 0; it < 4; it++) {
                int i = tid + it * 512;
                uint32_t so = (uint32_t)(i >> 4) * TSTRIDE + (i & 15) * 16;
                *(uint4*)(dyn + so) = __ldg(ah4 + i);
                *(uint4*)(dyn + TILE_BYTES + so) = __ldg(al4 + i);
            }
        }
        __syncthreads();

        // ---- MMA pass 1 ----
        float acc[2][4][4];
        #pragma unroll
        for (int ma = 0; ma < 2; ma++)
            #pragma unroll
            for (int na = 0; na < 4; na++)
                #pragma unroll
                for (int q = 0; q < 4; q++) acc[ma][na][q] = 0.f;

        #pragma unroll
        for (int ks = 0; ks < 8; ks++) {
            uint32_t kb = ks * 32;
            uint32_t ah[2][4], al[2][4], bh[4][2], bl[4][2];
            ldsm4(ah[0], aAddr + kb);
            ldsm4(ah[1], aAddr + 16 * TSTRIDE + kb);
            ldsm4(al[0], aAddr + TILE_BYTES + kb);
            ldsm4(al[1], aAddr + TILE_BYTES + 16 * TSTRIDE + kb);
            #pragma unroll
            for (int na = 0; na < 4; na++) {
                ldsm2(bh[na], bAddr1 + na * 8 * TSTRIDE + kb);
                ldsm2(bl[na], bAddr1 + TILE_BYTES + na * 8 * TSTRIDE + kb);
            }
            #pragma unroll
            for (int ma = 0; ma < 2; ma++)
                #pragma unroll
                for (int na = 0; na < 4; na++) {
                    mma16816(acc[ma][na], ah[ma], bh[na]);
                    mma16816(acc[ma][na], ah[ma], bl[na]);
                    mma16816(acc[ma][na], al[ma], bh[na]);
                }
        }
        __syncthreads();   // all warps done reading A tile

        // epilogue 1: scale/shift + ReLU, split, Z -> A smem
        #pragma unroll
        for (int ma = 0; ma < 2; ma++) {
            int lr1 = wm * 32 + ma * 16 + g4;
            int lr2 = lr1 + 8;
            #pragma unroll
            for (int na = 0; na < 4; na++) {
                int col = wn * 32 + na * 8 + 2 * tig;
                float sc0 = s_sc[col], sc1 = s_sc[col + 1];
                float sh0 = s_sh[col], sh1 = s_sh[col + 1];
                float o0 = fmaxf(fmaf(acc[ma][na][0], sc0, sh0), 0.f);
                float o1 = fmaxf(fmaf(acc[ma][na][1], sc1, sh1), 0.f);
                float o2 = fmaxf(fmaf(acc[ma][na][2], sc0, sh0), 0.f);
                float o3 = fmaxf(fmaf(acc[ma][na][3], sc1, sh1), 0.f);
                float q0, q1;
                uint32_t so1 = (uint32_t)lr1 * TSTRIDE + col * 2;
                uint32_t so2 = (uint32_t)lr2 * TSTRIDE + col * 2;
                *(uint32_t*)(dyn + so1) = pack_bf16(o0, o1, &q0, &q1);
                *(uint32_t*)(dyn + TILE_BYTES + so1) = pack_bf16_rn(q0, q1);
                *(uint32_t*)(dyn + so2) = pack_bf16(o2, o3, &q0, &q1);
                *(uint32_t*)(dyn + TILE_BYTES + so2) = pack_bf16_rn(q0, q1);
            }
        }
        __syncthreads();

        // ---- MMA pass 2 ----
        #pragma unroll
        for (int ma = 0; ma < 2; ma++)
            #pragma unroll
            for (int na = 0; na < 4; na++)
                #pragma unroll
                for (int q = 0; q < 4; q++) acc[ma][na][q] = 0.f;

        #pragma unroll
        for (int ks = 0; ks < 8; ks++) {
            uint32_t kb = ks * 32;
            uint32_t ah[2][4], al[2][4], bh[4][2], bl[4][2];
            ldsm4(ah[0], aAddr + kb);
            ldsm4(ah[1], aAddr + 16 * TSTRIDE + kb);
            ldsm4(al[0], aAddr + TILE_BYTES + kb);
            ldsm4(al[1], aAddr + TILE_BYTES + 16 * TSTRIDE + kb);
            #pragma unroll
            for (int na = 0; na < 4; na++) {
                ldsm2(bh[na], bAddr2 + na * 8 * TSTRIDE + kb);
                ldsm2(bl[na], bAddr2 + TILE_BYTES + na * 8 * TSTRIDE + kb);
            }
            #pragma unroll
            for (int ma = 0; ma < 2; ma++)
                #pragma unroll
                for (int na = 0; na < 4; na++) {
                    mma16816(acc[ma][na], ah[ma], bh[na]);
                    mma16816(acc[ma][na], ah[ma], bl[na]);
                    mma16816(acc[ma][na], al[ma], bh[na]);
                }
        }

        // epilogue 2: bias + ReLU -> fp32 or split bf16
        #pragma unroll
        for (int ma = 0; ma < 2; ma++) {
            int r1 = row0 + wm * 32 + ma * 16 + g4;
            int r2 = r1 + 8;
            #pragma unroll
            for (int na = 0; na < 4; na++) {
                int col = wn * 32 + na * 8 + 2 * tig;
                float sh0 = s_b2[col], sh1 = s_b2[col + 1];
                float o0 = fmaxf(acc[ma][na][0] + sh0, 0.f);
                float o1 = fmaxf(acc[ma][na][1] + sh1, 0.f);
                float o2 = fmaxf(acc[ma][na][2] + sh0, 0.f);
                float o3 = fmaxf(acc[ma][na][3] + sh1, 0.f);
                if (OUTBF) {
                    if (r1 < M) {
                        float q0, q1;
                        *(uint32_t*)(Ohi + (size_t)r1 * DIM + col) = pack_bf16(o0, o1, &q0, &q1);
                        *(uint32_t*)(Olo + (size_t)r1 * DIM + col) = pack_bf16_rn(q0, q1);
                    }
                    if (r2 < M) {
                        float q0, q1;
                        *(uint32_t*)(Ohi + (size_t)r2 * DIM + col) = pack_bf16(o2, o3, &q0, &q1);
                        *(uint32_t*)(Olo + (size_t)r2 * DIM + col) = pack_bf16_rn(q0, q1);
                    }
                } else {
                    if (r1 < M) *(float2*)(Hout + (size_t)r1 * DIM + col) = make_float2(o0, o1);
                    if (r2 < M) *(float2*)(Hout + (size_t)r2 * DIM + col) = make_float2(o2, o3);
                }
            }
        }
    }
}

// ---------------- classifier projections ----------------
__global__ void pq_kernel(const float* __restrict__ h, const float* __restrict__ clsW,
                          const float* __restrict__ clsb) {
    __shared__ float sW[256 * NC];
    int tid = threadIdx.x;
    for (int i = tid; i < 256 * NC; i += blockDim.x) sW[i] = clsW[i];
    __syncthreads();
    int w = (blockIdx.x * blockDim.x + tid) >> 5;
    int lane = tid & 31;
    if (w >= Nn) return;
    float4 a = __ldg(&((const float4*)h)[(size_t)w * 32 + lane]);
    int r = lane * 4;
    float accP[NC], accQ[NC];
    #pragma unroll
    for (int c = 0; c < NC; c++) {
        accP[c] = a.x * sW[r * NC + c] + a.y * sW[(r + 1) * NC + c]
                + a.z * sW[(r + 2) * NC + c] + a.w * sW[(r + 3) * NC + c];
        accQ[c] = a.x * sW[(128 + r) * NC + c] + a.y * sW[(129 + r) * NC + c]
                + a.z * sW[(130 + r) * NC + c] + a.w * sW[(131 + r) * NC + c];
    }
    #pragma unroll
    for (int off = 16; off > 0; off >>= 1) {
        #pragma unroll
        for (int c = 0; c < NC; c++) {
            accP[c] += __shfl_xor_sync(0xffffffffu, accP[c], off);
            accQ[c] += __shfl_xor_sync(0xffffffffu, accQ[c], off);
        }
    }
    if (lane == 0) {
        #pragma unroll
        for (int c = 0; c < NC; c++) {
            g_p[w * 8 + c] = accP[c] + clsb[c];
            g_q[w * 8 + c] = accQ[c];
        }
    }
}

// ---------------- final: e = concat(h[src],h[dst]); out = p[src]+q[dst] ----------------
__global__ void final_kernel(const float* __restrict__ h, const int* __restrict__ ei,
                             float* __restrict__ out0, float* __restrict__ eout) {
    int gt = blockIdx.x * blockDim.x + threadIdx.x;
    int e = gt >> 5, lane = gt & 31;
    if (e >= Ee) return;
    int s = ei[e], d = ei[Ee + e];
    const float4* hp = (const float4*)h;
    float4 a = __ldg(&hp[(size_t)s * 32 + lane]);
    float4 b = __ldg(&hp[(size_t)d * 32 + lane]);
    float4* ep = (float4*)(eout + (size_t)e * 256);
    __stcs(&ep[lane], a);
    __stcs(&ep[32 + lane], b);
    if (lane < NC) out0[(size_t)e * NC + lane] = g_p[s * 8 + lane] + g_q[d * 8 + lane];
}

// ---------------- launch ----------------
extern "C" void kernel_launch(void* const* d_in, const int* in_sizes, int n_in,
                              void* d_out, int out_size) {
    const float* x     = (const float*)d_in[0];
    const int*   ei    = (const int*)d_in[1];
    const float* c1_W1 = (const float*)d_in[3];
    const float* c1_b1 = (const float*)d_in[4];
    const float* c1_g  = (const float*)d_in[5];
    const float* c1_be = (const float*)d_in[6];
    const float* c1_rm = (const float*)d_in[7];
    const float* c1_rv = (const float*)d_in[8];
    const float* c1_W2 = (const float*)d_in[9];
    const float* c1_b2 = (const float*)d_in[10];
    const float* cv_W1 = (const float*)d_in[11];
    const float* cv_b1 = (const float*)d_in[12];
    const float* cv_g  = (const float*)d_in[13];
    const float* cv_be = (const float*)d_in[14];
    const float* cv_rm = (const float*)d_in[15];
    const float* cv_rv = (const float*)d_in[16];
    const float* cv_W2 = (const float*)d_in[17];
    const float* cv_b2 = (const float*)d_in[18];
    const float* lin_W = (const float*)d_in[19];
    const float* lin_b = (const float*)d_in[20];
    const float* cls_W = (const float*)d_in[21];
    const float* cls_b = (const float*)d_in[22];

    float* out0 = (float*)d_out;
    float* eout = out0 + (size_t)Ee * NC;

    void *ph, *pxh, *pxl, *px2h, *px2l, *pwh, *pwl;
    cudaGetSymbolAddress(&ph, g_h);
    cudaGetSymbolAddress(&pxh, g_xhi);
    cudaGetSymbolAddress(&pxl, g_xlo);
    cudaGetSymbolAddress(&px2h, g_x2hi);
    cudaGetSymbolAddress(&px2l, g_x2lo);
    cudaGetSymbolAddress(&pwh, g_Whi);
    cudaGetSymbolAddress(&pwl, g_Wlo);
    float* H = (float*)ph;
    __nv_bfloat16* XH = (__nv_bfloat16*)pxh;
    __nv_bfloat16* XL = (__nv_bfloat16*)pxl;
    __nv_bfloat16* X2H = (__nv_bfloat16*)px2h;
    __nv_bfloat16* X2L = (__nv_bfloat16*)px2l;
    const __nv_bfloat16* WH = (const __nv_bfloat16*)pwh;
    const __nv_bfloat16* WL = (const __nv_bfloat16*)pwl;

    const int NT = Nn2 / 128;                 // 391 tiles
    const int GG = 148;
    const int AGG_B = (Nn * 32 + 255) / 256;
    const int FIN_B = (Ee * 32 + 255) / 256;
    const int SMEM_F = 6 * TILE_BYTES;        // 208896

    cudaFuncSetAttribute(fused_mlp<0, 0>, cudaFuncAttributeMaxDynamicSharedMemorySize, SMEM_F);
    cudaFuncSetAttribute(fused_mlp<0, 1>, cudaFuncAttributeMaxDynamicSharedMemorySize, SMEM_F);
    cudaFuncSetAttribute(fused_mlp<1, 0>, cudaFuncAttributeMaxDynamicSharedMemorySize, SMEM_F);

    // CSR build + weight prep
    zero_cnt_kernel<<<(Nn / 4 + 255) / 256, 256>>>();
    count_kernel<<<(Ee + 255) / 256, 256>>>(ei);
    scan1_kernel<<<SCAN_NB, 512>>>();
    scan2_kernel<<<1, 128>>>();
    scan3_kernel<<<SCAN_NB, 512>>>();
    scatter_kernel<<<(Ee + 255) / 256, 256>>>(ei);
    prep_w_kernel<<<512, 256>>>(c1_W1, c1_W2,
                                cv_W1, cv_W1 + DIM * DIM,
                                cv_W2, cv_W2 + DIM * DIM,
                                lin_W, lin_W + DIM * DIM);
    // slots: 0=c1_W1 1=c1_W2 2=cvW1[0] 3=cvW1[1] 4=cvW2[0] 5=cvW2[1] 6=linW[0] 7=linW[1]

    // GIN1: agg(x) -> X; MLP(X) -> H
    agg_kernel<<<AGG_B, 256>>>(x, XH, XL);
    fused_mlp<0, 0><<<GG, 512, SMEM_F>>>(XH, XL, WH + 0 * 16384, WL + 0 * 16384,
                                         WH + 1 * 16384, WL + 1 * 16384,
                                         c1_b1, c1_g, c1_be, c1_rm, c1_rv, c1_b2,
                                         H, 0, 0, Nn, NT);
    // GIN2: agg(H) -> X; MLP(X) -> H
    agg_kernel<<<AGG_B, 256>>>(H, XH, XL);
    fused_mlp<0, 0><<<GG, 512, SMEM_F>>>(XH, XL, WH + 2 * 16384, WL + 2 * 16384,
                                         WH + 4 * 16384, WL + 4 * 16384,
                                         cv_b1, cv_g, cv_be, cv_rm, cv_rv, cv_b2,
                                         H, 0, 0, Nn, NT);
    // GIN3: agg(H) -> X; MLP(X) -> X2 (split)
    agg_kernel<<<AGG_B, 256>>>(H, XH, XL);
    fused_mlp<0, 1><<<GG, 512, SMEM_F>>>(XH, XL, WH + 3 * 16384, WL + 3 * 16384,
                                         WH + 5 * 16384, WL + 5 * 16384,
                                         cv_b1 + DIM, cv_g + DIM, cv_be + DIM,
                                         cv_rm + DIM, cv_rv + DIM, cv_b2 + DIM,
                                         0, X2H, X2L, Nn, NT);
    // linear layers: MLP(X2) -> H
    fused_mlp<1, 0><<<GG, 512, SMEM_F>>>(X2H, X2L, WH + 6 * 16384, WL + 6 * 16384,
                                         WH + 7 * 16384, WL + 7 * 16384,
                                         lin_b, 0, 0, 0, 0, lin_b + DIM,
                                         H, 0, 0, Nn, NT);

    // classifier
    pq_kernel<<<AGG_B, 256>>>(H, cls_W, cls_b);
    final_kernel<<<FIN_B, 256>>>(H, ei, out0, eout);
}

// round 6
// speedup vs baseline: 1.9842x; 1.0874x over previous
#include <cuda_runtime.h>
#include <cuda_bf16.h>
#include <cstdint>

#define Nn 50000
#define Nn2 50048
#define Ee 640000
#define DIM 128
#define NC 6

#define TSTRIDE 272                 // smem bytes per tile row (136 halves)
#define TILE_BYTES (128 * TSTRIDE)  // 34816
#define PQ_TILE (16 * TSTRIDE)      // 4352
#define SCAN_NB 98                  // ceil(50000/512)

typedef unsigned long long ull;

// ---------------- device scratch ----------------
__device__ float g_h[Nn * DIM];     // fp32 activations (final input)
__device__ float g_p[Nn * 8];
__device__ float g_q[Nn * 8];
__device__ int   g_rowptr[Nn + 1];
__device__ int   g_cnt[Nn];
__device__ int   g_bsum[128];
__device__ int   g_neigh[Ee];
// pre-split bf16 activations (rows >= Nn stay zero: never written)
__device__ __align__(16) __nv_bfloat16 g_xhi[Nn2 * DIM];
__device__ __align__(16) __nv_bfloat16 g_xlo[Nn2 * DIM];
__device__ __align__(16) __nv_bfloat16 g_x2hi[Nn2 * DIM];
__device__ __align__(16) __nv_bfloat16 g_x2lo[Nn2 * DIM];
__device__ __align__(16) __nv_bfloat16 g_Whi[8 * DIM * DIM];
__device__ __align__(16) __nv_bfloat16 g_Wlo[8 * DIM * DIM];
// classifier tile [16][128]: rows 0-5 = W_top cols, rows 8-13 = W_bot cols, rest 0
__device__ __align__(16) __nv_bfloat16 g_W3hi[16 * DIM];
__device__ __align__(16) __nv_bfloat16 g_W3lo[16 * DIM];

// ---------------- helpers ----------------
__device__ __forceinline__ uint32_t smem_u32(const void* p) {
    uint32_t a;
    asm("{ .reg .u64 t; cvta.to.shared.u64 t, %1; cvt.u32.u64 %0, t; }" : "=r"(a) : "l"(p));
    return a;
}
__device__ __forceinline__ void ldsm4(uint32_t* r, uint32_t addr) {
    asm volatile("ldmatrix.sync.aligned.m8n8.x4.shared.b16 {%0,%1,%2,%3}, [%4];"
                 : "=r"(r[0]), "=r"(r[1]), "=r"(r[2]), "=r"(r[3]) : "r"(addr));
}
__device__ __forceinline__ void ldsm2(uint32_t* r, uint32_t addr) {
    asm volatile("ldmatrix.sync.aligned.m8n8.x2.shared.b16 {%0,%1}, [%2];"
                 : "=r"(r[0]), "=r"(r[1]) : "r"(addr));
}
__device__ __forceinline__ void mma16816(float* c, const uint32_t* a, const uint32_t* b) {
    asm volatile(
        "mma.sync.aligned.m16n8k16.row.col.f32.bf16.bf16.f32 "
        "{%0,%1,%2,%3}, {%4,%5,%6,%7}, {%8,%9}, {%0,%1,%2,%3};"
        : "+f"(c[0]), "+f"(c[1]), "+f"(c[2]), "+f"(c[3])
        : "r"(a[0]), "r"(a[1]), "r"(a[2]), "r"(a[3]), "r"(b[0]), "r"(b[1]));
}
__device__ __forceinline__ uint32_t pack_bf16(float a, float b, float* ra, float* rb) {
    __nv_bfloat16 ha = __float2bfloat16(a);
    __nv_bfloat16 hb = __float2bfloat16(b);
    *ra = a - __bfloat162float(ha);
    *rb = b - __bfloat162float(hb);
    unsigned short ua = *(unsigned short*)&ha, ub = *(unsigned short*)&hb;
    return (uint32_t)ua | ((uint32_t)ub << 16);
}
__device__ __forceinline__ uint32_t pack_bf16_rn(float a, float b) {
    __nv_bfloat162 p = __floats2bfloat162_rn(a, b);
    return *(uint32_t*)&p;
}

// ---------------- prep: weights split/transpose + classifier tile + zero counts ----------------
__global__ void prep_kernel(const float* w0, const float* w1, const float* w2,
                            const float* w3, const float* w4, const float* w5,
                            const float* w6, const float* w7, const float* clsW) {
    int idx = blockIdx.x * blockDim.x + threadIdx.x;
    if (idx < Nn / 4) ((int4*)g_cnt)[idx] = make_int4(0, 0, 0, 0);
    if (idx < 16 * DIM) {
        int n = idx >> 7, k = idx & 127;
        float v = 0.f;
        if (n < 6) v = clsW[k * NC + n];
        else if (n >= 8 && n < 14) v = clsW[(128 + k) * NC + (n - 8)];
        __nv_bfloat16 h = __float2bfloat16(v);
        g_W3hi[idx] = h;
        g_W3lo[idx] = __float2bfloat16(v - __bfloat162float(h));
    }
    if (idx >= 8 * DIM * DIM) return;
    const float* ws[8] = {w0, w1, w2, w3, w4, w5, w6, w7};
    int g = idx >> 14, e = idx & 16383;
    int n = e >> 7, k = e & 127;
    float v = ws[g][k * DIM + n];
    __nv_bfloat16 h = __float2bfloat16(v);
    g_Whi[g * 16384 + e] = h;
    g_Wlo[g * 16384 + e] = __float2bfloat16(v - __bfloat162float(h));
}

// ---------------- CSR build ----------------
__global__ void count_kernel(const int* __restrict__ ei) {
    int t = blockIdx.x * blockDim.x + threadIdx.x;
    if (t < Ee / 4) {
        int4 d = __ldg((const int4*)(ei + Ee) + t);
        atomicAdd(&g_cnt[d.x], 1);
        atomicAdd(&g_cnt[d.y], 1);
        atomicAdd(&g_cnt[d.z], 1);
        atomicAdd(&g_cnt[d.w], 1);
    }
}

__global__ void scan1_kernel() {
    __shared__ int ws[16];
    int tid = threadIdx.x, lane = tid & 31, w = tid >> 5;
    int i = blockIdx.x * 512 + tid;
    int v = (i < Nn) ? g_cnt[i] : 0;
    int x = v;
    #pragma unroll
    for (int off = 1; off < 32; off <<= 1) {
        int y = __shfl_up_sync(0xffffffffu, x, off);
        if (lane >= off) x += y;
    }
    if (lane == 31) ws[w] = x;
    __syncthreads();
    if (w == 0) {
        int t = (lane < 16) ? ws[lane] : 0;
        #pragma unroll
        for (int off = 1; off < 16; off <<= 1) {
            int y = __shfl_up_sync(0xffffffffu, t, off);
            if (lane >= off) t += y;
        }
        if (lane < 16) ws[lane] = t;
    }
    __syncthreads();
    int excl = (w ? ws[w - 1] : 0) + x - v;
    if (i < Nn) { g_rowptr[i] = excl; g_cnt[i] = 0; }
    if (tid == 0) g_bsum[blockIdx.x] = ws[15];
}

// adds prefix-of-block-sums (computed in-block) to rowptr
__global__ void scan3_kernel() {
    __shared__ int ws[4];
    __shared__ int s_off;
    int tid = threadIdx.x, lane = tid & 31, w = tid >> 5;
    int b = blockIdx.x;
    if (tid < 128) {
        int v = (tid < b) ? g_bsum[tid] : 0;
        #pragma unroll
        for (int off = 16; off > 0; off >>= 1)
            v += __shfl_xor_sync(0xffffffffu, v, off);
        if (lane == 0) ws[w] = v;
    }
    __syncthreads();
    if (tid == 0) s_off = ws[0] + ws[1] + ws[2] + ws[3];
    __syncthreads();
    int i = b * 512 + tid;
    if (i < Nn) g_rowptr[i] += s_off;
    if (b == 0 && tid == 0) g_rowptr[Nn] = Ee;
}

__global__ void scatter_kernel(const int* __restrict__ ei) {
    int e = blockIdx.x * blockDim.x + threadIdx.x;
    if (e < Ee) {
        int d = ei[Ee + e];
        int slot = atomicAdd(&g_cnt[d], 1);
        g_neigh[g_rowptr[d] + slot] = ei[e];
    }
}

// ---------------- aggregation: (xhi,xlo) = split(h[i] + sum_{j->i} h[j]) ----------------
__global__ void agg_kernel(const float* __restrict__ hin,
                           __nv_bfloat16* __restrict__ xhi,
                           __nv_bfloat16* __restrict__ xlo) {
    int w = (blockIdx.x * blockDim.x + threadIdx.x) >> 5;
    int lane = threadIdx.x & 31;
    if (w >= Nn) return;
    const float4* hp = (const float4*)hin;
    float4 a = __ldg(&hp[(size_t)w * 32 + lane]);
    float x0 = a.x, x1 = a.y, x2 = a.z, x3 = a.w;
    int beg = g_rowptr[w], end = g_rowptr[w + 1];
    int e = beg;
    for (; e + 3 < end; e += 4) {
        int j0 = g_neigh[e], j1 = g_neigh[e + 1];
        int j2 = g_neigh[e + 2], j3 = g_neigh[e + 3];
        float4 v0 = __ldg(&hp[(size_t)j0 * 32 + lane]);
        float4 v1 = __ldg(&hp[(size_t)j1 * 32 + lane]);
        float4 v2 = __ldg(&hp[(size_t)j2 * 32 + lane]);
        float4 v3 = __ldg(&hp[(size_t)j3 * 32 + lane]);
        x0 += v0.x + v1.x + v2.x + v3.x;
        x1 += v0.y + v1.y + v2.y + v3.y;
        x2 += v0.z + v1.z + v2.z + v3.z;
        x3 += v0.w + v1.w + v2.w + v3.w;
    }
    for (; e < end; e++) {
        int j = g_neigh[e];
        float4 v = __ldg(&hp[(size_t)j * 32 + lane]);
        x0 += v.x; x1 += v.y; x2 += v.z; x3 += v.w;
    }
    float r0, r1, r2, r3;
    uint2 hw, lw;
    hw.x = pack_bf16(x0, x1, &r0, &r1);
    hw.y = pack_bf16(x2, x3, &r2, &r3);
    lw.x = pack_bf16_rn(r0, r1);
    lw.y = pack_bf16_rn(r2, r3);
    size_t off = (size_t)w * DIM + lane * 4;
    *(uint2*)(xhi + off) = hw;
    *(uint2*)(xlo + off) = lw;
}

// ---------------- fused dual-GEMM MLP (+ optional classifier MMA pass) ----------------
// MODE1 0: epilogue1 = BN+ReLU; 1: bias+ReLU.
// OUTBF 0: epilogue2 -> fp32 Hout; 1: -> split bf16 (Ohi/Olo).
// PQ 1: after epilogue2, run N=16 classifier MMA on final H, emit g_p/g_q.
template <int MODE1, int OUTBF, int PQ>
__global__ __launch_bounds__(512, 1) void fused_mlp(
    const __nv_bfloat16* __restrict__ Ahi_g, const __nv_bfloat16* __restrict__ Alo_g,
    const __nv_bfloat16* __restrict__ B1h, const __nv_bfloat16* __restrict__ B1l,
    const __nv_bfloat16* __restrict__ B2h, const __nv_bfloat16* __restrict__ B2l,
    const float* __restrict__ b1, const float* __restrict__ gg,
    const float* __restrict__ be, const float* __restrict__ rm,
    const float* __restrict__ rv, const float* __restrict__ b2,
    const float* __restrict__ clsb,
    float* __restrict__ Hout, __nv_bfloat16* __restrict__ Ohi,
    __nv_bfloat16* __restrict__ Olo, int M, int ntiles)
{
    extern __shared__ __align__(16) char dyn[];
    __shared__ float s_sc[DIM], s_sh[DIM], s_b2[DIM], s_cb[8];

    const int tid = threadIdx.x, lane = tid & 31, wid = tid >> 5;
    const uint32_t sbase = smem_u32(dyn);

    if (tid < DIM) {
        int c = tid;
        if (MODE1 == 0) {
            float s = gg[c] * rsqrtf(rv[c] + 1e-5f);
            s_sc[c] = s;
            s_sh[c] = (b1[c] - rm[c]) * s + be[c];
        } else {
            s_sc[c] = 1.0f;
            s_sh[c] = b1[c];
        }
        s_b2[c] = b2[c];
    }
    if (PQ && tid < 8) s_cb[tid] = (tid < 6) ? clsb[tid] : 0.f;

    {   // weight tiles once (persistent block)
        const uint4* p1h = (const uint4*)B1h;
        const uint4* p1l = (const uint4*)B1l;
        const uint4* p2h = (const uint4*)B2h;
        const uint4* p2l = (const uint4*)B2l;
        #pragma unroll
        for (int it = 0; it < 4; it++) {
            int i = tid + it * 512;
            uint32_t so = (uint32_t)(i >> 4) * TSTRIDE + (i & 15) * 16;
            *(uint4*)(dyn + 2 * TILE_BYTES + so) = __ldg(p1h + i);
            *(uint4*)(dyn + 3 * TILE_BYTES + so) = __ldg(p1l + i);
            *(uint4*)(dyn + 4 * TILE_BYTES + so) = __ldg(p2h + i);
            *(uint4*)(dyn + 5 * TILE_BYTES + so) = __ldg(p2l + i);
        }
        if (PQ && tid < 256) {   // classifier tile 16x128 bf16 hi/lo
            uint32_t so = (uint32_t)(tid >> 4) * TSTRIDE + (tid & 15) * 16;
            *(uint4*)(dyn + 6 * TILE_BYTES + so) = __ldg((const uint4*)g_W3hi + tid);
            *(uint4*)(dyn + 6 * TILE_BYTES + PQ_TILE + so) = __ldg((const uint4*)g_W3lo + tid);
        }
    }

    const int wm = wid >> 2, wn = wid & 3;
    const uint32_t aAddr = sbase + (uint32_t)(wm * 32 + (lane & 15)) * TSTRIDE + (lane >> 4) * 16;
    const uint32_t bAddr1 = sbase + 2 * TILE_BYTES +
                            (uint32_t)(wn * 32 + (lane & 7)) * TSTRIDE + ((lane >> 3) & 1) * 16;
    const uint32_t bAddr2 = bAddr1 + 2 * TILE_BYTES;
    const uint32_t bAddr3 = sbase + 6 * TILE_BYTES +
                            (uint32_t)(lane & 7) * TSTRIDE + ((lane >> 3) & 1) * 16;
    const int g4 = lane >> 2, tig = lane & 3;
    // PQ warps: one per SMSP, one per wm band: wid 0,5,10,15
    const bool pqWarp = PQ && ((wid & 3) == (wid >> 2));

    for (int t = blockIdx.x; t < ntiles; t += gridDim.x) {
        int row0 = t * 128;
        __syncthreads();   // prior-tile readers of A smem done

        {   // A tiles: straight uint4 copies
            const uint4* ah4 = (const uint4*)(Ahi_g + (size_t)row0 * DIM);
            const uint4* al4 = (const uint4*)(Alo_g + (size_t)row0 * DIM);
            #pragma unroll
            for (int it = 0; it < 4; it++) {
                int i = tid + it * 512;
                uint32_t so = (uint32_t)(i >> 4) * TSTRIDE + (i & 15) * 16;
                *(uint4*)(dyn + so) = __ldg(ah4 + i);
                *(uint4*)(dyn + TILE_BYTES + so) = __ldg(al4 + i);
            }
        }
        __syncthreads();

        // ---- MMA pass 1 ----
        float acc[2][4][4];
        #pragma unroll
        for (int ma = 0; ma < 2; ma++)
            #pragma unroll
            for (int na = 0; na < 4; na++)
                #pragma unroll
                for (int q = 0; q < 4; q++) acc[ma][na][q] = 0.f;

        #pragma unroll
        for (int ks = 0; ks < 8; ks++) {
            uint32_t kb = ks * 32;
            uint32_t ah[2][4], al[2][4], bh[4][2], bl[4][2];
            ldsm4(ah[0], aAddr + kb);
            ldsm4(ah[1], aAddr + 16 * TSTRIDE + kb);
            ldsm4(al[0], aAddr + TILE_BYTES + kb);
            ldsm4(al[1], aAddr + TILE_BYTES + 16 * TSTRIDE + kb);
            #pragma unroll
            for (int na = 0; na < 4; na++) {
                ldsm2(bh[na], bAddr1 + na * 8 * TSTRIDE + kb);
                ldsm2(bl[na], bAddr1 + TILE_BYTES + na * 8 * TSTRIDE + kb);
            }
            #pragma unroll
            for (int ma = 0; ma < 2; ma++)
                #pragma unroll
                for (int na = 0; na < 4; na++) {
                    mma16816(acc[ma][na], ah[ma], bh[na]);
                    mma16816(acc[ma][na], ah[ma], bl[na]);
                    mma16816(acc[ma][na], al[ma], bh[na]);
                }
        }
        __syncthreads();   // all warps done reading A tile

        // epilogue 1: scale/shift + ReLU, split, Z -> A smem
        #pragma unroll
        for (int ma = 0; ma < 2; ma++) {
            int lr1 = wm * 32 + ma * 16 + g4;
            int lr2 = lr1 + 8;
            #pragma unroll
            for (int na = 0; na < 4; na++) {
                int col = wn * 32 + na * 8 + 2 * tig;
                float sc0 = s_sc[col], sc1 = s_sc[col + 1];
                float sh0 = s_sh[col], sh1 = s_sh[col + 1];
                float o0 = fmaxf(fmaf(acc[ma][na][0], sc0, sh0), 0.f);
                float o1 = fmaxf(fmaf(acc[ma][na][1], sc1, sh1), 0.f);
                float o2 = fmaxf(fmaf(acc[ma][na][2], sc0, sh0), 0.f);
                float o3 = fmaxf(fmaf(acc[ma][na][3], sc1, sh1), 0.f);
                float q0, q1;
                uint32_t so1 = (uint32_t)lr1 * TSTRIDE + col * 2;
                uint32_t so2 = (uint32_t)lr2 * TSTRIDE + col * 2;
                *(uint32_t*)(dyn + so1) = pack_bf16(o0, o1, &q0, &q1);
                *(uint32_t*)(dyn + TILE_BYTES + so1) = pack_bf16_rn(q0, q1);
                *(uint32_t*)(dyn + so2) = pack_bf16(o2, o3, &q0, &q1);
                *(uint32_t*)(dyn + TILE_BYTES + so2) = pack_bf16_rn(q0, q1);
            }
        }
        __syncthreads();

        // ---- MMA pass 2 ----
        #pragma unroll
        for (int ma = 0; ma < 2; ma++)
            #pragma unroll
            for (int na = 0; na < 4; na++)
                #pragma unroll
                for (int q = 0; q < 4; q++) acc[ma][na][q] = 0.f;

        #pragma unroll
        for (int ks = 0; ks < 8; ks++) {
            uint32_t kb = ks * 32;
            uint32_t ah[2][4], al[2][4], bh[4][2], bl[4][2];
            ldsm4(ah[0], aAddr + kb);
            ldsm4(ah[1], aAddr + 16 * TSTRIDE + kb);
            ldsm4(al[0], aAddr + TILE_BYTES + kb);
            ldsm4(al[1], aAddr + TILE_BYTES + 16 * TSTRIDE + kb);
            #pragma unroll
            for (int na = 0; na < 4; na++) {
                ldsm2(bh[na], bAddr2 + na * 8 * TSTRIDE + kb);
                ldsm2(bl[na], bAddr2 + TILE_BYTES + na * 8 * TSTRIDE + kb);
            }
            #pragma unroll
            for (int ma = 0; ma < 2; ma++)
                #pragma unroll
                for (int na = 0; na < 4; na++) {
                    mma16816(acc[ma][na], ah[ma], bh[na]);
                    mma16816(acc[ma][na], ah[ma], bl[na]);
                    mma16816(acc[ma][na], al[ma], bh[na]);
                }
        }
        if (PQ) __syncthreads();   // all warps done reading Z before H-split overwrites it

        // epilogue 2: bias + ReLU -> fp32 / split bf16; PQ: also H-split -> A smem
        #pragma unroll
        for (int ma = 0; ma < 2; ma++) {
            int r1 = row0 + wm * 32 + ma * 16 + g4;
            int r2 = r1 + 8;
            int lr1 = wm * 32 + ma * 16 + g4;
            int lr2 = lr1 + 8;
            #pragma unroll
            for (int na = 0; na < 4; na++) {
                int col = wn * 32 + na * 8 + 2 * tig;
                float sh0 = s_b2[col], sh1 = s_b2[col + 1];
                float o0 = fmaxf(acc[ma][na][0] + sh0, 0.f);
                float o1 = fmaxf(acc[ma][na][1] + sh1, 0.f);
                float o2 = fmaxf(acc[ma][na][2] + sh0, 0.f);
                float o3 = fmaxf(acc[ma][na][3] + sh1, 0.f);
                if (PQ) {
                    float q0, q1;
                    uint32_t so1 = (uint32_t)lr1 * TSTRIDE + col * 2;
                    uint32_t so2 = (uint32_t)lr2 * TSTRIDE + col * 2;
                    *(uint32_t*)(dyn + so1) = pack_bf16(o0, o1, &q0, &q1);
                    *(uint32_t*)(dyn + TILE_BYTES + so1) = pack_bf16_rn(q0, q1);
                    *(uint32_t*)(dyn + so2) = pack_bf16(o2, o3, &q0, &q1);
                    *(uint32_t*)(dyn + TILE_BYTES + so2) = pack_bf16_rn(q0, q1);
                }
                if (OUTBF) {
                    if (r1 < M) {
                        float q0, q1;
                        *(uint32_t*)(Ohi + (size_t)r1 * DIM + col) = pack_bf16(o0, o1, &q0, &q1);
                        *(uint32_t*)(Olo + (size_t)r1 * DIM + col) = pack_bf16_rn(q0, q1);
                    }
                    if (r2 < M) {
                        float q0, q1;
                        *(uint32_t*)(Ohi + (size_t)r2 * DIM + col) = pack_bf16(o2, o3, &q0, &q1);
                        *(uint32_t*)(Olo + (size_t)r2 * DIM + col) = pack_bf16_rn(q0, q1);
                    }
                } else {
                    if (r1 < M) *(float2*)(Hout + (size_t)r1 * DIM + col) = make_float2(o0, o1);
                    if (r2 < M) *(float2*)(Hout + (size_t)r2 * DIM + col) = make_float2(o2, o3);
                }
            }
        }

        if (PQ) {
            __syncthreads();   // H-split visible
            if (pqWarp) {
                float acc3[2][2][4];
                #pragma unroll
                for (int ma = 0; ma < 2; ma++)
                    #pragma unroll
                    for (int na = 0; na < 2; na++)
                        #pragma unroll
                        for (int q = 0; q < 4; q++) acc3[ma][na][q] = 0.f;
                #pragma unroll
                for (int ks = 0; ks < 8; ks++) {
                    uint32_t kb = ks * 32;
                    uint32_t ah[2][4], al[2][4], b3h[2][2], b3l[2][2];
                    ldsm4(ah[0], aAddr + kb);
                    ldsm4(ah[1], aAddr + 16 * TSTRIDE + kb);
                    ldsm4(al[0], aAddr + TILE_BYTES + kb);
                    ldsm4(al[1], aAddr + TILE_BYTES + 16 * TSTRIDE + kb);
                    #pragma unroll
                    for (int na = 0; na < 2; na++) {
                        ldsm2(b3h[na], bAddr3 + na * 8 * TSTRIDE + kb);
                        ldsm2(b3l[na], bAddr3 + PQ_TILE + na * 8 * TSTRIDE + kb);
                    }
                    #pragma unroll
                    for (int ma = 0; ma < 2; ma++)
                        #pragma unroll
                        for (int na = 0; na < 2; na++) {
                            mma16816(acc3[ma][na], ah[ma], b3h[na]);
                            mma16816(acc3[ma][na], ah[ma], b3l[na]);
                            mma16816(acc3[ma][na], al[ma], b3h[na]);
                        }
                }
                // emit p (na=0, +bias) and q (na=1)
                #pragma unroll
                for (int ma = 0; ma < 2; ma++) {
                    int r1 = row0 + wm * 32 + ma * 16 + g4;
                    int r2 = r1 + 8;
                    int c0 = 2 * tig;
                    if (r1 < M) {
                        *(float2*)(g_p + (size_t)r1 * 8 + c0) =
                            make_float2(acc3[ma][0][0] + s_cb[c0], acc3[ma][0][1] + s_cb[c0 + 1]);
                        *(float2*)(g_q + (size_t)r1 * 8 + c0) =
                            make_float2(acc3[ma][1][0], acc3[ma][1][1]);
                    }
                    if (r2 < M) {
                        *(float2*)(g_p + (size_t)r2 * 8 + c0) =
                            make_float2(acc3[ma][0][2] + s_cb[c0], acc3[ma][0][3] + s_cb[c0 + 1]);
                        *(float2*)(g_q + (size_t)r2 * 8 + c0) =
                            make_float2(acc3[ma][1][2], acc3[ma][1][3]);
                    }
                }
            }
        }
    }
}

// ---------------- final: e = concat(h[src],h[dst]); out = p[src]+q[dst] ----------------
__global__ void final_kernel(const float* __restrict__ h, const int* __restrict__ ei,
                             float* __restrict__ out0, float* __restrict__ eout) {
    int gt = blockIdx.x * blockDim.x + threadIdx.x;
    int e = gt >> 5, lane = gt & 31;
    if (e >= Ee) return;
    int s = ei[e], d = ei[Ee + e];
    const float4* hp = (const float4*)h;
    float4 a = __ldg(&hp[(size_t)s * 32 + lane]);
    float4 b = __ldg(&hp[(size_t)d * 32 + lane]);
    float4* ep = (float4*)(eout + (size_t)e * 256);
    __stcs(&ep[lane], a);
    __stcs(&ep[32 + lane], b);
    if (lane < NC) out0[(size_t)e * NC + lane] = g_p[s * 8 + lane] + g_q[d * 8 + lane];
}

// ---------------- launch ----------------
extern "C" void kernel_launch(void* const* d_in, const int* in_sizes, int n_in,
                              void* d_out, int out_size) {
    const float* x     = (const float*)d_in[0];
    const int*   ei    = (const int*)d_in[1];
    const float* c1_W1 = (const float*)d_in[3];
    const float* c1_b1 = (const float*)d_in[4];
    const float* c1_g  = (const float*)d_in[5];
    const float* c1_be = (const float*)d_in[6];
    const float* c1_rm = (const float*)d_in[7];
    const float* c1_rv = (const float*)d_in[8];
    const float* c1_W2 = (const float*)d_in[9];
    const float* c1_b2 = (const float*)d_in[10];
    const float* cv_W1 = (const float*)d_in[11];
    const float* cv_b1 = (const float*)d_in[12];
    const float* cv_g  = (const float*)d_in[13];
    const float* cv_be = (const float*)d_in[14];
    const float* cv_rm = (const float*)d_in[15];
    const float* cv_rv = (const float*)d_in[16];
    const float* cv_W2 = (const float*)d_in[17];
    const float* cv_b2 = (const float*)d_in[18];
    const float* lin_W = (const float*)d_in[19];
    const float* lin_b = (const float*)d_in[20];
    const float* cls_W = (const float*)d_in[21];
    const float* cls_b = (const float*)d_in[22];

    float* out0 = (float*)d_out;
    float* eout = out0 + (size_t)Ee * NC;

    void *ph, *pxh, *pxl, *px2h, *px2l, *pwh, *pwl;
    cudaGetSymbolAddress(&ph, g_h);
    cudaGetSymbolAddress(&pxh, g_xhi);
    cudaGetSymbolAddress(&pxl, g_xlo);
    cudaGetSymbolAddress(&px2h, g_x2hi);
    cudaGetSymbolAddress(&px2l, g_x2lo);
    cudaGetSymbolAddress(&pwh, g_Whi);
    cudaGetSymbolAddress(&pwl, g_Wlo);
    float* H = (float*)ph;
    __nv_bfloat16* XH = (__nv_bfloat16*)pxh;
    __nv_bfloat16* XL = (__nv_bfloat16*)pxl;
    __nv_bfloat16* X2H = (__nv_bfloat16*)px2h;
    __nv_bfloat16* X2L = (__nv_bfloat16*)px2l;
    const __nv_bfloat16* WH = (const __nv_bfloat16*)pwh;
    const __nv_bfloat16* WL = (const __nv_bfloat16*)pwl;

    const int NT = Nn2 / 128;                 // 391 tiles
    const int GG = 148;
    const int AGG_B = (Nn * 32 + 255) / 256;
    const int FIN_B = (Ee * 32 + 255) / 256;
    const int SMEM_F  = 6 * TILE_BYTES;               // 208896
    const int SMEM_FP = 6 * TILE_BYTES + 2 * PQ_TILE; // 217600

    cudaFuncSetAttribute(fused_mlp<0, 0, 0>, cudaFuncAttributeMaxDynamicSharedMemorySize, SMEM_F);
    cudaFuncSetAttribute(fused_mlp<0, 1, 0>, cudaFuncAttributeMaxDynamicSharedMemorySize, SMEM_F);
    cudaFuncSetAttribute(fused_mlp<1, 0, 1>, cudaFuncAttributeMaxDynamicSharedMemorySize, SMEM_FP);

    // prep (weights split + cls tile + zero counts), then CSR build
    prep_kernel<<<512, 256>>>(c1_W1, c1_W2,
                              cv_W1, cv_W1 + DIM * DIM,
                              cv_W2, cv_W2 + DIM * DIM,
                              lin_W, lin_W + DIM * DIM, cls_W);
    count_kernel<<<(Ee / 4 + 255) / 256, 256>>>(ei);
    scan1_kernel<<<SCAN_NB, 512>>>();
    scan3_kernel<<<SCAN_NB, 512>>>();
    scatter_kernel<<<(Ee + 255) / 256, 256>>>(ei);
    // slots: 0=c1_W1 1=c1_W2 2=cvW1[0] 3=cvW1[1] 4=cvW2[0] 5=cvW2[1] 6=linW[0] 7=linW[1]

    // GIN1: agg(x) -> X; MLP(X) -> H
    agg_kernel<<<AGG_B, 256>>>(x, XH, XL);
    fused_mlp<0, 0, 0><<<GG, 512, SMEM_F>>>(XH, XL, WH + 0 * 16384, WL + 0 * 16384,
                                            WH + 1 * 16384, WL + 1 * 16384,
                                            c1_b1, c1_g, c1_be, c1_rm, c1_rv, c1_b2, 0,
                                            H, 0, 0, Nn, NT);
    // GIN2
    agg_kernel<<<AGG_B, 256>>>(H, XH, XL);
    fused_mlp<0, 0, 0><<<GG, 512, SMEM_F>>>(XH, XL, WH + 2 * 16384, WL + 2 * 16384,
                                            WH + 4 * 16384, WL + 4 * 16384,
                                            cv_b1, cv_g, cv_be, cv_rm, cv_rv, cv_b2, 0,
                                            H, 0, 0, Nn, NT);
    // GIN3 -> split X2
    agg_kernel<<<AGG_B, 256>>>(H, XH, XL);
    fused_mlp<0, 1, 0><<<GG, 512, SMEM_F>>>(XH, XL, WH + 3 * 16384, WL + 3 * 16384,
                                            WH + 5 * 16384, WL + 5 * 16384,
                                            cv_b1 + DIM, cv_g + DIM, cv_be + DIM,
                                            cv_rm + DIM, cv_rv + DIM, cv_b2 + DIM, 0,
                                            0, X2H, X2L, Nn, NT);
    // linear layers + fused classifier: MLP(X2) -> H, p, q
    fused_mlp<1, 0, 1><<<GG, 512, SMEM_FP>>>(X2H, X2L, WH + 6 * 16384, WL + 6 * 16384,
                                             WH + 7 * 16384, WL + 7 * 16384,
                                             lin_b, 0, 0, 0, 0, lin_b + DIM, cls_b,
                                             H, 0, 0, Nn, NT);

    // edge output
    final_kernel<<<FIN_B, 256>>>(H, ei, out0, eout);
}

// round 7
// speedup vs baseline: 2.0012x; 1.0086x over previous
#include <cuda_runtime.h>
#include <cuda_bf16.h>
#include <cstdint>

#define Nn 50000
#define Nn2 50048
#define Ee 640000
#define DIM 128
#define NC 6

#define TSTRIDE 272                 // smem bytes per tile row (136 halves)
#define TILE_BYTES (128 * TSTRIDE)  // 34816
#define PQ_TILE (16 * TSTRIDE)      // 4352
#define SCAN_NB 98                  // ceil(50000/512)

typedef unsigned long long ull;

// ---------------- device scratch ----------------
__device__ float g_h[Nn * DIM];     // fp32 activations (final input)
__device__ float g_p[Nn * 8];
__device__ float g_q[Nn * 8];
__device__ int   g_rowptr[Nn + 1];
__device__ int   g_cnt[Nn];         // zero-init; self-restoring per launch
__device__ int   g_bsum[128];
__device__ int   g_neigh[Ee];
// pre-split bf16 activations (rows >= Nn stay zero: never written)
__device__ __align__(16) __nv_bfloat16 g_xhi[Nn2 * DIM];
__device__ __align__(16) __nv_bfloat16 g_xlo[Nn2 * DIM];
__device__ __align__(16) __nv_bfloat16 g_x2hi[Nn2 * DIM];
__device__ __align__(16) __nv_bfloat16 g_x2lo[Nn2 * DIM];
__device__ __align__(16) __nv_bfloat16 g_Whi[8 * DIM * DIM];
__device__ __align__(16) __nv_bfloat16 g_Wlo[8 * DIM * DIM];
// classifier tile [16][128]: rows 0-5 = W_top cols, rows 8-13 = W_bot cols, rest 0
__device__ __align__(16) __nv_bfloat16 g_W3hi[16 * DIM];
__device__ __align__(16) __nv_bfloat16 g_W3lo[16 * DIM];

// ---------------- helpers ----------------
__device__ __forceinline__ uint32_t smem_u32(const void* p) {
    uint32_t a;
    asm("{ .reg .u64 t; cvta.to.shared.u64 t, %1; cvt.u32.u64 %0, t; }" : "=r"(a) : "l"(p));
    return a;
}
__device__ __forceinline__ void ldsm4(uint32_t* r, uint32_t addr) {
    asm volatile("ldmatrix.sync.aligned.m8n8.x4.shared.b16 {%0,%1,%2,%3}, [%4];"
                 : "=r"(r[0]), "=r"(r[1]), "=r"(r[2]), "=r"(r[3]) : "r"(addr));
}
__device__ __forceinline__ void mma16816(float* c, const uint32_t* a, const uint32_t* b) {
    asm volatile(
        "mma.sync.aligned.m16n8k16.row.col.f32.bf16.bf16.f32 "
        "{%0,%1,%2,%3}, {%4,%5,%6,%7}, {%8,%9}, {%0,%1,%2,%3};"
        : "+f"(c[0]), "+f"(c[1]), "+f"(c[2]), "+f"(c[3])
        : "r"(a[0]), "r"(a[1]), "r"(a[2]), "r"(a[3]), "r"(b[0]), "r"(b[1]));
}
__device__ __forceinline__ uint32_t pack_bf16(float a, float b, float* ra, float* rb) {
    __nv_bfloat16 ha = __float2bfloat16(a);
    __nv_bfloat16 hb = __float2bfloat16(b);
    *ra = a - __bfloat162float(ha);
    *rb = b - __bfloat162float(hb);
    unsigned short ua = *(unsigned short*)&ha, ub = *(unsigned short*)&hb;
    return (uint32_t)ua | ((uint32_t)ub << 16);
}
__device__ __forceinline__ uint32_t pack_bf16_rn(float a, float b) {
    __nv_bfloat162 p = __floats2bfloat162_rn(a, b);
    return *(uint32_t*)&p;
}

// ---------------- prep: weights split/transpose + classifier tile ----------------
__global__ void prep_kernel(const float* w0, const float* w1, const float* w2,
                            const float* w3, const float* w4, const float* w5,
                            const float* w6, const float* w7, const float* clsW) {
    int idx = blockIdx.x * blockDim.x + threadIdx.x;
    if (idx < 16 * DIM) {
        int n = idx >> 7, k = idx & 127;
        float v = 0.f;
        if (n < 6) v = clsW[k * NC + n];
        else if (n >= 8 && n < 14) v = clsW[(128 + k) * NC + (n - 8)];
        __nv_bfloat16 h = __float2bfloat16(v);
        g_W3hi[idx] = h;
        g_W3lo[idx] = __float2bfloat16(v - __bfloat162float(h));
    }
    if (idx >= 8 * DIM * DIM) return;
    const float* ws[8] = {w0, w1, w2, w3, w4, w5, w6, w7};
    int g = idx >> 14, e = idx & 16383;
    int n = e >> 7, k = e & 127;
    float v = ws[g][k * DIM + n];
    __nv_bfloat16 h = __float2bfloat16(v);
    g_Whi[g * 16384 + e] = h;
    g_Wlo[g * 16384 + e] = __float2bfloat16(v - __bfloat162float(h));
}

// ---------------- CSR build (g_cnt self-restores to 0 each launch) ----------------
__global__ void count_kernel(const int* __restrict__ ei) {
    int t = blockIdx.x * blockDim.x + threadIdx.x;
    if (t < Ee / 4) {
        int4 d = __ldg((const int4*)(ei + Ee) + t);
        atomicAdd(&g_cnt[d.x], 1);
        atomicAdd(&g_cnt[d.y], 1);
        atomicAdd(&g_cnt[d.z], 1);
        atomicAdd(&g_cnt[d.w], 1);
    }
}

__global__ void scan1_kernel() {
    __shared__ int ws[16];
    int tid = threadIdx.x, lane = tid & 31, w = tid >> 5;
    int i = blockIdx.x * 512 + tid;
    int v = (i < Nn) ? g_cnt[i] : 0;
    int x = v;
    #pragma unroll
    for (int off = 1; off < 32; off <<= 1) {
        int y = __shfl_up_sync(0xffffffffu, x, off);
        if (lane >= off) x += y;
    }
    if (lane == 31) ws[w] = x;
    __syncthreads();
    if (w == 0) {
        int t = (lane < 16) ? ws[lane] : 0;
        #pragma unroll
        for (int off = 1; off < 16; off <<= 1) {
            int y = __shfl_up_sync(0xffffffffu, t, off);
            if (lane >= off) t += y;
        }
        if (lane < 16) ws[lane] = t;
    }
    __syncthreads();
    int excl = (w ? ws[w - 1] : 0) + x - v;
    if (i < Nn) g_rowptr[i] = excl;
    if (tid == 0) g_bsum[blockIdx.x] = ws[15];
}

// adds prefix-of-block-sums (computed in-block) to rowptr
__global__ void scan3_kernel() {
    __shared__ int ws[4];
    __shared__ int s_off;
    int tid = threadIdx.x, lane = tid & 31, w = tid >> 5;
    int b = blockIdx.x;
    if (tid < 128) {
        int v = (tid < b) ? g_bsum[tid] : 0;
        #pragma unroll
        for (int off = 16; off > 0; off >>= 1)
            v += __shfl_xor_sync(0xffffffffu, v, off);
        if (lane == 0) ws[w] = v;
    }
    __syncthreads();
    if (tid == 0) s_off = ws[0] + ws[1] + ws[2] + ws[3];
    __syncthreads();
    int i = b * 512 + tid;
    if (i < Nn) g_rowptr[i] += s_off;
    if (b == 0 && tid == 0) g_rowptr[Nn] = Ee;
}

__global__ void scatter_kernel(const int* __restrict__ ei) {
    int e = blockIdx.x * blockDim.x + threadIdx.x;
    if (e < Ee) {
        int d = ei[Ee + e];
        int slot = atomicSub(&g_cnt[d], 1) - 1;   // counts -> 0 (self-restoring)
        g_neigh[g_rowptr[d] + slot] = ei[e];
    }
}

// ---------------- aggregation: (xhi,xlo) = split(h[i] + sum_{j->i} h[j]) ----------------
__global__ void agg_kernel(const float* __restrict__ hin,
                           __nv_bfloat16* __restrict__ xhi,
                           __nv_bfloat16* __restrict__ xlo) {
    int w = (blockIdx.x * blockDim.x + threadIdx.x) >> 5;
    int lane = threadIdx.x & 31;
    if (w >= Nn) return;
    const float4* hp = (const float4*)hin;
    float4 a = __ldg(&hp[(size_t)w * 32 + lane]);
    float x0 = a.x, x1 = a.y, x2 = a.z, x3 = a.w;
    int beg = g_rowptr[w], end = g_rowptr[w + 1];
    int e = beg;
    for (; e + 3 < end; e += 4) {
        int j0 = g_neigh[e], j1 = g_neigh[e + 1];
        int j2 = g_neigh[e + 2], j3 = g_neigh[e + 3];
        float4 v0 = __ldg(&hp[(size_t)j0 * 32 + lane]);
        float4 v1 = __ldg(&hp[(size_t)j1 * 32 + lane]);
        float4 v2 = __ldg(&hp[(size_t)j2 * 32 + lane]);
        float4 v3 = __ldg(&hp[(size_t)j3 * 32 + lane]);
        x0 += v0.x + v1.x + v2.x + v3.x;
        x1 += v0.y + v1.y + v2.y + v3.y;
        x2 += v0.z + v1.z + v2.z + v3.z;
        x3 += v0.w + v1.w + v2.w + v3.w;
    }
    for (; e < end; e++) {
        int j = g_neigh[e];
        float4 v = __ldg(&hp[(size_t)j * 32 + lane]);
        x0 += v.x; x1 += v.y; x2 += v.z; x3 += v.w;
    }
    float r0, r1, r2, r3;
    uint2 hw, lw;
    hw.x = pack_bf16(x0, x1, &r0, &r1);
    hw.y = pack_bf16(x2, x3, &r2, &r3);
    lw.x = pack_bf16_rn(r0, r1);
    lw.y = pack_bf16_rn(r2, r3);
    size_t off = (size_t)w * DIM + lane * 4;
    *(uint2*)(xhi + off) = hw;
    *(uint2*)(xlo + off) = lw;
}

// ---------------- fused dual-GEMM MLP (+ optional classifier MMA pass) ----------------
// MODE1 0: epilogue1 = BN+ReLU; 1: bias+ReLU.
// OUTBF 0: epilogue2 -> fp32 Hout; 1: -> split bf16 (Ohi/Olo).
// PQ 1: after epilogue2, run N=16 classifier MMA on final H, emit g_p/g_q.
template <int MODE1, int OUTBF, int PQ>
__global__ __launch_bounds__(512, 1) void fused_mlp(
    const __nv_bfloat16* __restrict__ Ahi_g, const __nv_bfloat16* __restrict__ Alo_g,
    const __nv_bfloat16* __restrict__ B1h, const __nv_bfloat16* __restrict__ B1l,
    const __nv_bfloat16* __restrict__ B2h, const __nv_bfloat16* __restrict__ B2l,
    const float* __restrict__ b1, const float* __restrict__ gg,
    const float* __restrict__ be, const float* __restrict__ rm,
    const float* __restrict__ rv, const float* __restrict__ b2,
    const float* __restrict__ clsb,
    float* __restrict__ Hout, __nv_bfloat16* __restrict__ Ohi,
    __nv_bfloat16* __restrict__ Olo, int M, int ntiles)
{
    extern __shared__ __align__(16) char dyn[];
    __shared__ float s_sc[DIM], s_sh[DIM], s_b2[DIM], s_cb[8];

    const int tid = threadIdx.x, lane = tid & 31, wid = tid >> 5;
    const uint32_t sbase = smem_u32(dyn);

    if (tid < DIM) {
        int c = tid;
        if (MODE1 == 0) {
            float s = gg[c] * rsqrtf(rv[c] + 1e-5f);
            s_sc[c] = s;
            s_sh[c] = (b1[c] - rm[c]) * s + be[c];
        } else {
            s_sc[c] = 1.0f;
            s_sh[c] = b1[c];
        }
        s_b2[c] = b2[c];
    }
    if (PQ && tid < 8) s_cb[tid] = (tid < 6) ? clsb[tid] : 0.f;

    {   // weight tiles once (persistent block)
        const uint4* p1h = (const uint4*)B1h;
        const uint4* p1l = (const uint4*)B1l;
        const uint4* p2h = (const uint4*)B2h;
        const uint4* p2l = (const uint4*)B2l;
        #pragma unroll
        for (int it = 0; it < 4; it++) {
            int i = tid + it * 512;
            uint32_t so = (uint32_t)(i >> 4) * TSTRIDE + (i & 15) * 16;
            *(uint4*)(dyn + 2 * TILE_BYTES + so) = __ldg(p1h + i);
            *(uint4*)(dyn + 3 * TILE_BYTES + so) = __ldg(p1l + i);
            *(uint4*)(dyn + 4 * TILE_BYTES + so) = __ldg(p2h + i);
            *(uint4*)(dyn + 5 * TILE_BYTES + so) = __ldg(p2l + i);
        }
        if (PQ && tid < 256) {   // classifier tile 16x128 bf16 hi/lo
            uint32_t so = (uint32_t)(tid >> 4) * TSTRIDE + (tid & 15) * 16;
            *(uint4*)(dyn + 6 * TILE_BYTES + so) = __ldg((const uint4*)g_W3hi + tid);
            *(uint4*)(dyn + 6 * TILE_BYTES + PQ_TILE + so) = __ldg((const uint4*)g_W3lo + tid);
        }
    }

    const int wm = wid >> 2, wn = wid & 3;
    const uint32_t aAddr = sbase + (uint32_t)(wm * 32 + (lane & 15)) * TSTRIDE + (lane >> 4) * 16;
    // B via ldsm4: lanes 0-7 -> [n0-7,klo], 8-15 -> [n0-7,khi], 16-23 -> [n8-15,klo], 24-31 -> [n8-15,khi]
    const int quad = lane >> 3;
    const uint32_t bRow = (uint32_t)((quad >> 1) * 8 + (lane & 7));
    const uint32_t bCol = (uint32_t)((quad & 1) * 16);
    const uint32_t bAddr1 = sbase + 2 * TILE_BYTES +
                            ((uint32_t)wn * 32 + bRow) * TSTRIDE + bCol;
    const uint32_t bAddr2 = bAddr1 + 2 * TILE_BYTES;
    const uint32_t bAddr3 = sbase + 6 * TILE_BYTES + bRow * TSTRIDE + bCol;
    const int g4 = lane >> 2, tig = lane & 3;
    // PQ warps: one per SMSP, one per wm band: wid 0,5,10,15
    const bool pqWarp = PQ && ((wid & 3) == (wid >> 2));

    for (int t = blockIdx.x; t < ntiles; t += gridDim.x) {
        int row0 = t * 128;
        __syncthreads();   // prior-tile readers of A smem done

        {   // A tiles: straight uint4 copies
            const uint4* ah4 = (const uint4*)(Ahi_g + (size_t)row0 * DIM);
            const uint4* al4 = (const uint4*)(Alo_g + (size_t)row0 * DIM);
            #pragma unroll
            for (int it = 0; it < 4; it++) {
                int i = tid + it * 512;
                uint32_t so = (uint32_t)(i >> 4) * TSTRIDE + (i & 15) * 16;
                *(uint4*)(dyn + so) = __ldg(ah4 + i);
                *(uint4*)(dyn + TILE_BYTES + so) = __ldg(al4 + i);
            }
        }
        __syncthreads();

        // ---- MMA pass 1 ----
        float acc[2][4][4];
        #pragma unroll
        for (int ma = 0; ma < 2; ma++)
            #pragma unroll
            for (int na = 0; na < 4; na++)
                #pragma unroll
                for (int q = 0; q < 4; q++) acc[ma][na][q] = 0.f;

        #pragma unroll
        for (int ks = 0; ks < 8; ks++) {
            uint32_t kb = ks * 32;
            uint32_t ah[2][4], al[2][4], bh[2][4], bl[2][4];
            ldsm4(ah[0], aAddr + kb);
            ldsm4(ah[1], aAddr + 16 * TSTRIDE + kb);
            ldsm4(al[0], aAddr + TILE_BYTES + kb);
            ldsm4(al[1], aAddr + TILE_BYTES + 16 * TSTRIDE + kb);
            ldsm4(bh[0], bAddr1 + kb);                         // n0-15: {r0,r1},{r2,r3}
            ldsm4(bh[1], bAddr1 + 16 * TSTRIDE + kb);          // n16-31
            ldsm4(bl[0], bAddr1 + TILE_BYTES + kb);
            ldsm4(bl[1], bAddr1 + TILE_BYTES + 16 * TSTRIDE + kb);
            #pragma unroll
            for (int ma = 0; ma < 2; ma++)
                #pragma unroll
                for (int na = 0; na < 4; na++) {
                    const uint32_t* pbh = &bh[na >> 1][(na & 1) * 2];
                    const uint32_t* pbl = &bl[na >> 1][(na & 1) * 2];
                    mma16816(acc[ma][na], ah[ma], pbh);
                    mma16816(acc[ma][na], ah[ma], pbl);
                    mma16816(acc[ma][na], al[ma], pbh);
                }
        }
        __syncthreads();   // all warps done reading A tile

        // epilogue 1: scale/shift + ReLU, split, Z -> A smem
        #pragma unroll
        for (int ma = 0; ma < 2; ma++) {
            int lr1 = wm * 32 + ma * 16 + g4;
            int lr2 = lr1 + 8;
            #pragma unroll
            for (int na = 0; na < 4; na++) {
                int col = wn * 32 + na * 8 + 2 * tig;
                float sc0 = s_sc[col], sc1 = s_sc[col + 1];
                float sh0 = s_sh[col], sh1 = s_sh[col + 1];
                float o0 = fmaxf(fmaf(acc[ma][na][0], sc0, sh0), 0.f);
                float o1 = fmaxf(fmaf(acc[ma][na][1], sc1, sh1), 0.f);
                float o2 = fmaxf(fmaf(acc[ma][na][2], sc0, sh0), 0.f);
                float o3 = fmaxf(fmaf(acc[ma][na][3], sc1, sh1), 0.f);
                float q0, q1;
                uint32_t so1 = (uint32_t)lr1 * TSTRIDE + col * 2;
                uint32_t so2 = (uint32_t)lr2 * TSTRIDE + col * 2;
                *(uint32_t*)(dyn + so1) = pack_bf16(o0, o1, &q0, &q1);
                *(uint32_t*)(dyn + TILE_BYTES + so1) = pack_bf16_rn(q0, q1);
                *(uint32_t*)(dyn + so2) = pack_bf16(o2, o3, &q0, &q1);
                *(uint32_t*)(dyn + TILE_BYTES + so2) = pack_bf16_rn(q0, q1);
            }
        }
        __syncthreads();

        // ---- MMA pass 2 ----
        #pragma unroll
        for (int ma = 0; ma < 2; ma++)
            #pragma unroll
            for (int na = 0; na < 4; na++)
                #pragma unroll
                for (int q = 0; q < 4; q++) acc[ma][na][q] = 0.f;

        #pragma unroll
        for (int ks = 0; ks < 8; ks++) {
            uint32_t kb = ks * 32;
            uint32_t ah[2][4], al[2][4], bh[2][4], bl[2][4];
            ldsm4(ah[0], aAddr + kb);
            ldsm4(ah[1], aAddr + 16 * TSTRIDE + kb);
            ldsm4(al[0], aAddr + TILE_BYTES + kb);
            ldsm4(al[1], aAddr + TILE_BYTES + 16 * TSTRIDE + kb);
            ldsm4(bh[0], bAddr2 + kb);
            ldsm4(bh[1], bAddr2 + 16 * TSTRIDE + kb);
            ldsm4(bl[0], bAddr2 + TILE_BYTES + kb);
            ldsm4(bl[1], bAddr2 + TILE_BYTES + 16 * TSTRIDE + kb);
            #pragma unroll
            for (int ma = 0; ma < 2; ma++)
                #pragma unroll
                for (int na = 0; na < 4; na++) {
                    const uint32_t* pbh = &bh[na >> 1][(na & 1) * 2];
                    const uint32_t* pbl = &bl[na >> 1][(na & 1) * 2];
                    mma16816(acc[ma][na], ah[ma], pbh);
                    mma16816(acc[ma][na], ah[ma], pbl);
                    mma16816(acc[ma][na], al[ma], pbh);
                }
        }
        if (PQ) __syncthreads();   // all warps done reading Z before H-split overwrites it

        // epilogue 2: bias + ReLU -> fp32 / split bf16; PQ: also H-split -> A smem
        #pragma unroll
        for (int ma = 0; ma < 2; ma++) {
            int r1 = row0 + wm * 32 + ma * 16 + g4;
            int r2 = r1 + 8;
            int lr1 = wm * 32 + ma * 16 + g4;
            int lr2 = lr1 + 8;
            #pragma unroll
            for (int na = 0; na < 4; na++) {
                int col = wn * 32 + na * 8 + 2 * tig;
                float sh0 = s_b2[col], sh1 = s_b2[col + 1];
                float o0 = fmaxf(acc[ma][na][0] + sh0, 0.f);
                float o1 = fmaxf(acc[ma][na][1] + sh1, 0.f);
                float o2 = fmaxf(acc[ma][na][2] + sh0, 0.f);
                float o3 = fmaxf(acc[ma][na][3] + sh1, 0.f);
                if (PQ) {
                    float q0, q1;
                    uint32_t so1 = (uint32_t)lr1 * TSTRIDE + col * 2;
                    uint32_t so2 = (uint32_t)lr2 * TSTRIDE + col * 2;
                    *(uint32_t*)(dyn + so1) = pack_bf16(o0, o1, &q0, &q1);
                    *(uint32_t*)(dyn + TILE_BYTES + so1) = pack_bf16_rn(q0, q1);
                    *(uint32_t*)(dyn + so2) = pack_bf16(o2, o3, &q0, &q1);
                    *(uint32_t*)(dyn + TILE_BYTES + so2) = pack_bf16_rn(q0, q1);
                }
                if (OUTBF) {
                    if (r1 < M) {
                        float q0, q1;
                        *(uint32_t*)(Ohi + (size_t)r1 * DIM + col) = pack_bf16(o0, o1, &q0, &q1);
                        *(uint32_t*)(Olo + (size_t)r1 * DIM + col) = pack_bf16_rn(q0, q1);
                    }
                    if (r2 < M) {
                        float q0, q1;
                        *(uint32_t*)(Ohi + (size_t)r2 * DIM + col) = pack_bf16(o2, o3, &q0, &q1);
                        *(uint32_t*)(Olo + (size_t)r2 * DIM + col) = pack_bf16_rn(q0, q1);
                    }
                } else {
                    if (r1 < M) *(float2*)(Hout + (size_t)r1 * DIM + col) = make_float2(o0, o1);
                    if (r2 < M) *(float2*)(Hout + (size_t)r2 * DIM + col) = make_float2(o2, o3);
                }
            }
        }

        if (PQ) {
            __syncthreads();   // H-split visible
            if (pqWarp) {
                float acc3[2][2][4];
                #pragma unroll
                for (int ma = 0; ma < 2; ma++)
                    #pragma unroll
                    for (int na = 0; na < 2; na++)
                        #pragma unroll
                        for (int q = 0; q < 4; q++) acc3[ma][na][q] = 0.f;
                #pragma unroll
                for (int ks = 0; ks < 8; ks++) {
                    uint32_t kb = ks * 32;
                    uint32_t ah[2][4], al[2][4], b3h[4], b3l[4];
                    ldsm4(ah[0], aAddr + kb);
                    ldsm4(ah[1], aAddr + 16 * TSTRIDE + kb);
                    ldsm4(al[0], aAddr + TILE_BYTES + kb);
                    ldsm4(al[1], aAddr + TILE_BYTES + 16 * TSTRIDE + kb);
                    ldsm4(b3h, bAddr3 + kb);            // {r0,r1}=p rows, {r2,r3}=q rows
                    ldsm4(b3l, bAddr3 + PQ_TILE + kb);
                    #pragma unroll
                    for (int ma = 0; ma < 2; ma++)
                        #pragma unroll
                        for (int na = 0; na < 2; na++) {
                            const uint32_t* pbh = &b3h[na * 2];
                            const uint32_t* pbl = &b3l[na * 2];
                            mma16816(acc3[ma][na], ah[ma], pbh);
                            mma16816(acc3[ma][na], ah[ma], pbl);
                            mma16816(acc3[ma][na], al[ma], pbh);
                        }
                }
                // emit p (na=0, +bias) and q (na=1)
                #pragma unroll
                for (int ma = 0; ma < 2; ma++) {
                    int r1 = row0 + wm * 32 + ma * 16 + g4;
                    int r2 = r1 + 8;
                    int c0 = 2 * tig;
                    if (r1 < M) {
                        *(float2*)(g_p + (size_t)r1 * 8 + c0) =
                            make_float2(acc3[ma][0][0] + s_cb[c0], acc3[ma][0][1] + s_cb[c0 + 1]);
                        *(float2*)(g_q + (size_t)r1 * 8 + c0) =
                            make_float2(acc3[ma][1][0], acc3[ma][1][1]);
                    }
                    if (r2 < M) {
                        *(float2*)(g_p + (size_t)r2 * 8 + c0) =
                            make_float2(acc3[ma][0][2] + s_cb[c0], acc3[ma][0][3] + s_cb[c0 + 1]);
                        *(float2*)(g_q + (size_t)r2 * 8 + c0) =
                            make_float2(acc3[ma][1][2], acc3[ma][1][3]);
                    }
                }
            }
        }
    }
}

// ---------------- final: e = concat(h[src],h[dst]); out = p[src]+q[dst] ----------------
__global__ void final_kernel(const float* __restrict__ h, const int* __restrict__ ei,
                             float* __restrict__ out0, float* __restrict__ eout) {
    int gt = blockIdx.x * blockDim.x + threadIdx.x;
    int e = gt >> 5, lane = gt & 31;
    if (e >= Ee) return;
    int s = ei[e], d = ei[Ee + e];
    const float4* hp = (const float4*)h;
    float4 a = __ldg(&hp[(size_t)s * 32 + lane]);
    float4 b = __ldg(&hp[(size_t)d * 32 + lane]);
    float4* ep = (float4*)(eout + (size_t)e * 256);
    __stcs(&ep[lane], a);
    __stcs(&ep[32 + lane], b);
    if (lane < NC) out0[(size_t)e * NC + lane] = g_p[s * 8 + lane] + g_q[d * 8 + lane];
}

// ---------------- launch ----------------
extern "C" void kernel_launch(void* const* d_in, const int* in_sizes, int n_in,
                              void* d_out, int out_size) {
    const float* x     = (const float*)d_in[0];
    const int*   ei    = (const int*)d_in[1];
    const float* c1_W1 = (const float*)d_in[3];
    const float* c1_b1 = (const float*)d_in[4];
    const float* c1_g  = (const float*)d_in[5];
    const float* c1_be = (const float*)d_in[6];
    const float* c1_rm = (const float*)d_in[7];
    const float* c1_rv = (const float*)d_in[8];
    const float* c1_W2 = (const float*)d_in[9];
    const float* c1_b2 = (const float*)d_in[10];
    const float* cv_W1 = (const float*)d_in[11];
    const float* cv_b1 = (const float*)d_in[12];
    const float* cv_g  = (const float*)d_in[13];
    const float* cv_be = (const float*)d_in[14];
    const float* cv_rm = (const float*)d_in[15];
    const float* cv_rv = (const float*)d_in[16];
    const float* cv_W2 = (const float*)d_in[17];
    const float* cv_b2 = (const float*)d_in[18];
    const float* lin_W = (const float*)d_in[19];
    const float* lin_b = (const float*)d_in[20];
    const float* cls_W = (const float*)d_in[21];
    const float* cls_b = (const float*)d_in[22];

    float* out0 = (float*)d_out;
    float* eout = out0 + (size_t)Ee * NC;

    void *ph, *pxh, *pxl, *px2h, *px2l, *pwh, *pwl;
    cudaGetSymbolAddress(&ph, g_h);
    cudaGetSymbolAddress(&pxh, g_xhi);
    cudaGetSymbolAddress(&pxl, g_xlo);
    cudaGetSymbolAddress(&px2h, g_x2hi);
    cudaGetSymbolAddress(&px2l, g_x2lo);
    cudaGetSymbolAddress(&pwh, g_Whi);
    cudaGetSymbolAddress(&pwl, g_Wlo);
    float* H = (float*)ph;
    __nv_bfloat16* XH = (__nv_bfloat16*)pxh;
    __nv_bfloat16* XL = (__nv_bfloat16*)pxl;
    __nv_bfloat16* X2H = (__nv_bfloat16*)px2h;
    __nv_bfloat16* X2L = (__nv_bfloat16*)px2l;
    const __nv_bfloat16* WH = (const __nv_bfloat16*)pwh;
    const __nv_bfloat16* WL = (const __nv_bfloat16*)pwl;

    const int NT = Nn2 / 128;                 // 391 tiles
    const int GG = 148;
    const int AGG_B = (Nn * 32 + 255) / 256;
    const int FIN_B = (Ee * 32 + 255) / 256;
    const int SMEM_F  = 6 * TILE_BYTES;               // 208896
    const int SMEM_FP = 6 * TILE_BYTES + 2 * PQ_TILE; // 217600

    cudaFuncSetAttribute(fused_mlp<0, 0, 0>, cudaFuncAttributeMaxDynamicSharedMemorySize, SMEM_F);
    cudaFuncSetAttribute(fused_mlp<0, 1, 0>, cudaFuncAttributeMaxDynamicSharedMemorySize, SMEM_F);
    cudaFuncSetAttribute(fused_mlp<1, 0, 1>, cudaFuncAttributeMaxDynamicSharedMemorySize, SMEM_FP);

    // prep + CSR build (g_cnt: zero at entry, counts after count, zero again after scatter)
    prep_kernel<<<512, 256>>>(c1_W1, c1_W2,
                              cv_W1, cv_W1 + DIM * DIM,
                              cv_W2, cv_W2 + DIM * DIM,
                              lin_W, lin_W + DIM * DIM, cls_W);
    count_kernel<<<(Ee / 4 + 255) / 256, 256>>>(ei);
    scan1_kernel<<<SCAN_NB, 512>>>();
    scan3_kernel<<<SCAN_NB, 512>>>();
    scatter_kernel<<<(Ee + 255) / 256, 256>>>(ei);
    // slots: 0=c1_W1 1=c1_W2 2=cvW1[0] 3=cvW1[1] 4=cvW2[0] 5=cvW2[1] 6=linW[0] 7=linW[1]

    // GIN1: agg(x) -> X; MLP(X) -> H
    agg_kernel<<<AGG_B, 256>>>(x, XH, XL);
    fused_mlp<0, 0, 0><<<GG, 512, SMEM_F>>>(XH, XL, WH + 0 * 16384, WL + 0 * 16384,
                                            WH + 1 * 16384, WL + 1 * 16384,
                                            c1_b1, c1_g, c1_be, c1_rm, c1_rv, c1_b2, 0,
                                            H, 0, 0, Nn, NT);
    // GIN2
    agg_kernel<<<AGG_B, 256>>>(H, XH, XL);
    fused_mlp<0, 0, 0><<<GG, 512, SMEM_F>>>(XH, XL, WH + 2 * 16384, WL + 2 * 16384,
                                            WH + 4 * 16384, WL + 4 * 16384,
                                            cv_b1, cv_g, cv_be, cv_rm, cv_rv, cv_b2, 0,
                                            H, 0, 0, Nn, NT);
    // GIN3 -> split X2
    agg_kernel<<<AGG_B, 256>>>(H, XH, XL);
    fused_mlp<0, 1, 0><<<GG, 512, SMEM_F>>>(XH, XL, WH + 3 * 16384, WL + 3 * 16384,
                                            WH + 5 * 16384, WL + 5 * 16384,
                                            cv_b1 + DIM, cv_g + DIM, cv_be + DIM,
                                            cv_rm + DIM, cv_rv + DIM, cv_b2 + DIM, 0,
                                            0, X2H, X2L, Nn, NT);
    // linear layers + fused classifier: MLP(X2) -> H, p, q
    fused_mlp<1, 0, 1><<<GG, 512, SMEM_FP>>>(X2H, X2L, WH + 6 * 16384, WL + 6 * 16384,
                                             WH + 7 * 16384, WL + 7 * 16384,
                                             lin_b, 0, 0, 0, 0, lin_b + DIM, cls_b,
                                             H, 0, 0, Nn, NT);

    // edge output
    final_kernel<<<FIN_B, 256>>>(H, ei, out0, eout);
}